// round 2
// baseline (speedup 1.0000x reference)
#include <cuda_runtime.h>

// ---------------- problem constants (fixed shapes) ----------------
namespace cfg {
constexpr int B = 2, T = 2048, C = 1024, H = 16, HS = 64;
constexpr int BT = B * T;     // 4096
constexpr int FF = 4 * C;     // 4096
constexpr float EPS = 1e-5f;
constexpr int NCHUNK = 16;    // T reduction chunks for layernorm
}

// ---------------- scratch (device globals; no allocs allowed) ----------------
__device__ float g_h1[(size_t)cfg::B * cfg::T * cfg::C];
__device__ float g_q [(size_t)cfg::B * cfg::H * cfg::T * cfg::HS];
__device__ float g_k [(size_t)cfg::B * cfg::H * cfg::T * cfg::HS];
__device__ float g_v [(size_t)cfg::B * cfg::H * cfg::T * cfg::HS];
__device__ float g_S [(size_t)cfg::B * cfg::H * cfg::T * cfg::T];   // 512 MB scores
__device__ float g_at[(size_t)cfg::B * cfg::T * cfg::C];
__device__ float g_x2[(size_t)cfg::B * cfg::T * cfg::C];
__device__ float g_h2[(size_t)cfg::B * cfg::T * cfg::C];
__device__ float g_f [(size_t)cfg::B * cfg::T * cfg::FF];
__device__ float g_ps[cfg::NCHUNK * cfg::B * cfg::C];
__device__ float g_pq[cfg::NCHUNK * cfg::B * cfg::C];
__device__ float g_mean[cfg::B * cfg::C];
__device__ float g_inv [cfg::B * cfg::C];

// ---------------- packed f32x2 helpers (sm_103a FFMA2 path) ----------------
typedef unsigned long long u64;

__device__ __forceinline__ void ffma2(u64& d, u64 a, u64 b) {
    asm("fma.rn.f32x2 %0, %1, %2, %0;" : "+l"(d) : "l"(a), "l"(b));
}
__device__ __forceinline__ u64 packdup(float x) {
    u64 r; asm("mov.b64 %0, {%1, %2};" : "=l"(r) : "f"(x), "f"(x)); return r;
}
__device__ __forceinline__ float2 unpk(u64 v) {
    float2 f; asm("mov.b64 {%0, %1}, %2;" : "=f"(f.x), "=f"(f.y) : "l"(v)); return f;
}

// ---------------- generic batched GEMM ----------------
// C[z] = alpha * A[z] @ op(B[z]) (+ bias) (relu?) (+ resid)
// A row-major [M,K] lda; B row-major [K,N] ldb (or [N,K] ldb when TRANSB);
// per-batch offsets: z -> (zb, zh) = (z/Hdiv, z%Hdiv), off = zb*s1 + zh*s2.
// Requires M%128==0, N%BN==0, K%16==0, all pointers 16B-aligned (true here).
template<int BN, int TN, bool TRANSB>
__global__ void __launch_bounds__(256)
gemm_f32x2(const float* __restrict__ Ag, const float* __restrict__ Bg,
           float* __restrict__ Cg, const float* __restrict__ bias,
           const float* __restrict__ resid,
           int M, int N, int K, int lda, int ldb, int ldc,
           long long sA1, long long sA2, long long sB1, long long sB2,
           long long sC1, long long sC2, int Hdiv, int biasStride,
           float alpha, int doRelu)
{
    constexpr int BM = 128, BK = 16, TM = 8;
    constexpr int KF4 = BK / 4;                         // 4
    constexpr int AF4 = BM * BK / 1024;                 // 2 float4 per thread
    constexpr int BF4 = BK * BN / 1024;                 // 2 (BN=128) or 1 (BN=64)

    __shared__ __align__(16) float As[BK][BM];
    __shared__ __align__(16) float Bs[BK][BN];

    const int z  = blockIdx.z;
    const int zb = z / Hdiv, zh = z - zb * Hdiv;
    const float* A  = Ag + (long long)zb * sA1 + (long long)zh * sA2;
    const float* Bp = Bg + (long long)zb * sB1 + (long long)zh * sB2;
    float*       Cp = Cg + (long long)zb * sC1 + (long long)zh * sC2;
    const float* Rp = resid ? resid + (long long)zb * sC1 + (long long)zh * sC2 : nullptr;
    const float* bv = bias ? bias + zh * biasStride : nullptr;

    const int tid = threadIdx.x;
    const int tx  = tid & 15;      // BN/TN == 16 for both configs
    const int ty  = tid >> 4;      // 0..15

    const int rowBase = blockIdx.y * BM;
    const int colBase = blockIdx.x * BN;

    u64 acc[TM][TN / 2];
    #pragma unroll
    for (int i = 0; i < TM; i++)
        #pragma unroll
        for (int j = 0; j < TN / 2; j++) acc[i][j] = 0ull;

    for (int kt = 0; kt < K; kt += BK) {
        // ---- A tile -> As[k][m] (transposed in smem) ----
        #pragma unroll
        for (int i = 0; i < AF4; i++) {
            int idx = tid + i * 256;
            int row = idx / KF4;
            int k0  = (idx % KF4) * 4;
            float4 f = *(const float4*)(A + (size_t)(rowBase + row) * lda + kt + k0);
            As[k0 + 0][row] = f.x; As[k0 + 1][row] = f.y;
            As[k0 + 2][row] = f.z; As[k0 + 3][row] = f.w;
        }
        // ---- B tile -> Bs[k][n] ----
        if (!TRANSB) {
            #pragma unroll
            for (int i = 0; i < BF4; i++) {
                int idx = tid + i * 256;
                int kr  = idx / (BN / 4);
                int nc  = (idx % (BN / 4)) * 4;
                *(float4*)&Bs[kr][nc] =
                    *(const float4*)(Bp + (size_t)(kt + kr) * ldb + colBase + nc);
            }
        } else {
            #pragma unroll
            for (int i = 0; i < BF4; i++) {
                int idx = tid + i * 256;
                int n   = idx / KF4;
                int k0  = (idx % KF4) * 4;
                float4 f = *(const float4*)(Bp + (size_t)(colBase + n) * ldb + kt + k0);
                Bs[k0 + 0][n] = f.x; Bs[k0 + 1][n] = f.y;
                Bs[k0 + 2][n] = f.z; Bs[k0 + 3][n] = f.w;
            }
        }
        __syncthreads();

        // ---- compute: 8x{8|4} per thread, packed f32x2 FMA ----
        #pragma unroll
        for (int k = 0; k < BK; k++) {
            float4 a0 = *(const float4*)&As[k][ty * 4];
            float4 a1 = *(const float4*)&As[k][ty * 4 + BM / 2];
            u64 bp[4];
            {
                ulonglong2 t0 = *(const ulonglong2*)&Bs[k][tx * 4];
                bp[0] = t0.x; bp[1] = t0.y;
                if (TN == 8) {
                    ulonglong2 t1 = *(const ulonglong2*)&Bs[k][tx * 4 + BN / 2];
                    bp[2] = t1.x; bp[3] = t1.y;
                }
            }
            float av[TM] = {a0.x, a0.y, a0.z, a0.w, a1.x, a1.y, a1.z, a1.w};
            #pragma unroll
            for (int i = 0; i < TM; i++) {
                u64 ad = packdup(av[i]);
                #pragma unroll
                for (int j = 0; j < TN / 2; j++) ffma2(acc[i][j], ad, bp[j]);
            }
        }
        __syncthreads();
    }

    // ---- epilogue: alpha, bias, relu, residual ----
    #pragma unroll
    for (int i = 0; i < TM; i++) {
        int row = rowBase + ty * 4 + (i & 3) + ((i >= 4) ? BM / 2 : 0);
        #pragma unroll
        for (int s = 0; s < TN / 4; s++) {
            int col = colBase + tx * 4 + s * (BN / 2);
            float2 v0 = unpk(acc[i][s * 2 + 0]);
            float2 v1 = unpk(acc[i][s * 2 + 1]);
            float4 o = make_float4(v0.x * alpha, v0.y * alpha,
                                   v1.x * alpha, v1.y * alpha);
            if (bv) {
                float4 bb = *(const float4*)&bv[col];
                o.x += bb.x; o.y += bb.y; o.z += bb.z; o.w += bb.w;
            }
            if (doRelu) {
                o.x = fmaxf(o.x, 0.f); o.y = fmaxf(o.y, 0.f);
                o.z = fmaxf(o.z, 0.f); o.w = fmaxf(o.w, 0.f);
            }
            size_t off = (size_t)row * ldc + col;
            if (Rp) {
                float4 r4 = *(const float4*)&Rp[off];
                o.x += r4.x; o.y += r4.y; o.z += r4.z; o.w += r4.w;
            }
            *(float4*)&Cp[off] = o;
        }
    }
}

// ---------------- LayerNorm over axis=1 (the T axis!), ddof=1, eps OUTSIDE sqrt ----
// stage 1: partial sums per (b,c) over T-chunks (deterministic, no atomics)
__global__ void ln_stats(const float* __restrict__ x,
                         float* __restrict__ ps, float* __restrict__ pq) {
    using namespace cfg;
    int gx = blockIdx.x;                 // 0..15 = b*8 + ctile
    int chunk = blockIdx.y;              // 0..15
    int b = gx >> 3, ct = gx & 7;
    int c = ct * 128 + threadIdx.x;
    const float* xp = x + ((size_t)b * T + (size_t)chunk * (T / NCHUNK)) * C + c;
    float s = 0.f, q = 0.f;
    #pragma unroll 4
    for (int r = 0; r < T / NCHUNK; r++) {
        float v = xp[(size_t)r * C];
        s += v; q += v * v;
    }
    int bc = b * C + c;
    ps[chunk * (B * C) + bc] = s;
    pq[chunk * (B * C) + bc] = q;
}

__global__ void ln_finalize(const float* __restrict__ ps, const float* __restrict__ pq,
                            float* __restrict__ meanb, float* __restrict__ invb) {
    using namespace cfg;
    int idx = blockIdx.x * blockDim.x + threadIdx.x;
    if (idx >= B * C) return;
    float s = 0.f, q = 0.f;
    #pragma unroll
    for (int ch = 0; ch < NCHUNK; ch++) {
        s += ps[ch * (B * C) + idx];
        q += pq[ch * (B * C) + idx];
    }
    float mean = s / (float)T;
    float var  = (q - s * s / (float)T) / (float)(T - 1);   // unbiased (ddof=1)
    meanb[idx] = mean;
    invb[idx]  = 1.f / (sqrtf(var) + EPS);                  // eps OUTSIDE sqrt
}

__global__ void ln_apply(const float* __restrict__ x, const float* __restrict__ meanb,
                         const float* __restrict__ invb, const float* __restrict__ gamma,
                         const float* __restrict__ beta, float* __restrict__ out) {
    using namespace cfg;
    size_t i4  = (size_t)blockIdx.x * blockDim.x + threadIdx.x;
    size_t idx = i4 * 4;
    int c  = (int)(idx % C);
    int b  = (int)(idx / ((size_t)T * C));
    int bc = b * C + c;
    float4 xv = *(const float4*)&x[idx];
    float4 gm = *(const float4*)&gamma[c];
    float4 bt = *(const float4*)&beta[c];
    float4 o;
    o.x = gm.x * ((xv.x - meanb[bc + 0]) * invb[bc + 0]) + bt.x;
    o.y = gm.y * ((xv.y - meanb[bc + 1]) * invb[bc + 1]) + bt.y;
    o.z = gm.z * ((xv.z - meanb[bc + 2]) * invb[bc + 2]) + bt.z;
    o.w = gm.w * ((xv.w - meanb[bc + 3]) * invb[bc + 3]) + bt.w;
    *(float4*)&out[idx] = o;
}

// ---------------- softmax over rows of S (row = 2048 contiguous floats) ----------------
__global__ void softmax_rows(float* __restrict__ S) {
    using namespace cfg;
    __shared__ float red[8];
    float* row = S + (size_t)blockIdx.x * T;
    int tid = threadIdx.x;
    float v[8];
    float mx = -3.4e38f;
    #pragma unroll
    for (int i = 0; i < 8; i++) { v[i] = row[tid + i * 256]; mx = fmaxf(mx, v[i]); }
    #pragma unroll
    for (int o = 16; o > 0; o >>= 1) mx = fmaxf(mx, __shfl_xor_sync(0xffffffffu, mx, o));
    if ((tid & 31) == 0) red[tid >> 5] = mx;
    __syncthreads();
    float m = red[0];
    #pragma unroll
    for (int w = 1; w < 8; w++) m = fmaxf(m, red[w]);
    __syncthreads();
    float s = 0.f;
    #pragma unroll
    for (int i = 0; i < 8; i++) { v[i] = __expf(v[i] - m); s += v[i]; }
    #pragma unroll
    for (int o = 16; o > 0; o >>= 1) s += __shfl_xor_sync(0xffffffffu, s, o);
    if ((tid & 31) == 0) red[tid >> 5] = s;
    __syncthreads();
    float tot = red[0];
    #pragma unroll
    for (int w = 1; w < 8; w++) tot += red[w];
    float inv = 1.f / tot;
    #pragma unroll
    for (int i = 0; i < 8; i++) row[tid + i * 256] = v[i] * inv;
}

// ---------------- launch ----------------
extern "C" void kernel_launch(void* const* d_in, const int* in_sizes, int n_in,
                              void* d_out, int out_size)
{
    using namespace cfg;
    const float* x   = (const float*)d_in[0];
    const float* Wq  = (const float*)d_in[1];
    const float* bq  = (const float*)d_in[2];
    const float* Wk  = (const float*)d_in[3];
    const float* bk  = (const float*)d_in[4];
    const float* Wv  = (const float*)d_in[5];
    const float* bvv = (const float*)d_in[6];
    const float* Wo  = (const float*)d_in[7];
    const float* bo  = (const float*)d_in[8];
    const float* W1  = (const float*)d_in[9];
    const float* b1  = (const float*)d_in[10];
    const float* W2  = (const float*)d_in[11];
    const float* b2  = (const float*)d_in[12];
    const float* g1  = (const float*)d_in[13];
    const float* be1 = (const float*)d_in[14];
    const float* g2  = (const float*)d_in[15];
    const float* be2 = (const float*)d_in[16];
    float* out = (float*)d_out;

    float *h1, *q, *k, *v, *S, *at, *x2, *h2, *f, *ps, *pq, *mean, *inv;
    cudaGetSymbolAddress((void**)&h1,   g_h1);
    cudaGetSymbolAddress((void**)&q,    g_q);
    cudaGetSymbolAddress((void**)&k,    g_k);
    cudaGetSymbolAddress((void**)&v,    g_v);
    cudaGetSymbolAddress((void**)&S,    g_S);
    cudaGetSymbolAddress((void**)&at,   g_at);
    cudaGetSymbolAddress((void**)&x2,   g_x2);
    cudaGetSymbolAddress((void**)&h2,   g_h2);
    cudaGetSymbolAddress((void**)&f,    g_f);
    cudaGetSymbolAddress((void**)&ps,   g_ps);
    cudaGetSymbolAddress((void**)&pq,   g_pq);
    cudaGetSymbolAddress((void**)&mean, g_mean);
    cudaGetSymbolAddress((void**)&inv,  g_inv);

    const long long TC   = (long long)T * C;
    const long long CHS  = (long long)C * HS;
    const long long THS  = (long long)T * HS;
    const long long HTHS = (long long)H * T * HS;
    const long long TT   = (long long)T * T;
    const long long HTT  = (long long)H * T * T;

    // ---- LN1: h1 = ln(x, gamma1, beta1)  (normalize over T) ----
    ln_stats<<<dim3(16, NCHUNK), 128>>>(x, ps, pq);
    ln_finalize<<<(B * C + 255) / 256, 256>>>(ps, pq, mean, inv);
    ln_apply<<<(B * T * C / 4) / 256, 256>>>(x, mean, inv, g1, be1, h1);

    // ---- QKV: [B,H,T,HS] = h1 @ W{q,k,v}[h] + b  (batched over (b,h)) ----
    dim3 gQKV(1, T / 128, B * H);
    gemm_f32x2<64, 4, false><<<gQKV, 256>>>(h1, Wq, q, bq, nullptr,
        T, HS, C, C, HS, HS,  TC, 0,  0, CHS,  HTHS, THS,  H, HS, 1.f, 0);
    gemm_f32x2<64, 4, false><<<gQKV, 256>>>(h1, Wk, k, bk, nullptr,
        T, HS, C, C, HS, HS,  TC, 0,  0, CHS,  HTHS, THS,  H, HS, 1.f, 0);
    gemm_f32x2<64, 4, false><<<gQKV, 256>>>(h1, Wv, v, bvv, nullptr,
        T, HS, C, C, HS, HS,  TC, 0,  0, CHS,  HTHS, THS,  H, HS, 1.f, 0);

    // ---- scores: S = (Q @ K^T) * HS^-0.5   (batched over B*H, B transposed) ----
    dim3 gS(T / 128, T / 128, B * H);
    gemm_f32x2<128, 8, true><<<gS, 256>>>(q, k, S, nullptr, nullptr,
        T, T, HS, HS, HS, T,  THS, 0,  THS, 0,  TT, 0,  1, 0, 0.125f, 0);

    // ---- softmax over keys ----
    softmax_rows<<<B * H * T, 256>>>(S);

    // ---- attn = S @ V, written head-concat into [B,T,C] ----
    gemm_f32x2<64, 4, false><<<gQKV, 256>>>(S, v, at, nullptr, nullptr,
        T, HS, T, T, HS, C,  HTT, TT,  HTHS, THS,  TC, (long long)HS,  H, 0, 1.f, 0);

    // ---- x2 = x + attn @ Wo + bo ----
    dim3 gWo(C / 128, BT / 128, 1);
    gemm_f32x2<128, 8, false><<<gWo, 256>>>(at, Wo, x2, bo, x,
        BT, C, C, C, C, C,  0, 0, 0, 0, 0, 0,  1, 0, 1.f, 0);

    // ---- LN2: h2 = ln(x2, gamma2, beta2) ----
    ln_stats<<<dim3(16, NCHUNK), 128>>>(x2, ps, pq);
    ln_finalize<<<(B * C + 255) / 256, 256>>>(ps, pq, mean, inv);
    ln_apply<<<(B * T * C / 4) / 256, 256>>>(x2, mean, inv, g2, be2, h2);

    // ---- FFN: out = x2 + relu(h2 @ W1 + b1) @ W2 + b2 ----
    dim3 gF1(FF / 128, BT / 128, 1);
    gemm_f32x2<128, 8, false><<<gF1, 256>>>(h2, W1, f, b1, nullptr,
        BT, FF, C, C, FF, FF,  0, 0, 0, 0, 0, 0,  1, 0, 1.f, 1);
    dim3 gF2(C / 128, BT / 128, 1);
    gemm_f32x2<128, 8, false><<<gF2, 256>>>(f, W2, out, b2, x2,
        BT, C, FF, FF, C, C,  0, 0, 0, 0, 0, 0,  1, 0, 1.f, 0);
}

// round 4
// speedup vs baseline: 2.2811x; 2.2811x over previous
#include <cuda_runtime.h>

// ---------------- problem constants (fixed shapes) ----------------
namespace cfg {
constexpr int B = 2, T = 2048, C = 1024, H = 16, HS = 64;
constexpr int BT = B * T;     // 4096
constexpr int FF = 4 * C;     // 4096
constexpr float EPS = 1e-5f;
constexpr int NCHUNK = 16;    // T reduction chunks for layernorm
}

// ---------------- scratch (device globals; no allocs allowed) ----------------
__device__ float g_h1[(size_t)cfg::B * cfg::T * cfg::C];
__device__ float g_q [(size_t)cfg::B * cfg::H * cfg::T * cfg::HS];
__device__ float g_k [(size_t)cfg::B * cfg::H * cfg::T * cfg::HS];
__device__ float g_v [(size_t)cfg::B * cfg::H * cfg::T * cfg::HS];
__device__ float g_S [(size_t)cfg::B * cfg::H * cfg::T * cfg::T];   // 512 MB scores
__device__ float g_at[(size_t)cfg::B * cfg::T * cfg::C];
__device__ float g_x2[(size_t)cfg::B * cfg::T * cfg::C];
__device__ float g_h2[(size_t)cfg::B * cfg::T * cfg::C];
__device__ float g_f [(size_t)cfg::B * cfg::T * cfg::FF];
__device__ float g_ps[cfg::NCHUNK * cfg::B * cfg::C];
__device__ float g_pq[cfg::NCHUNK * cfg::B * cfg::C];
__device__ float g_mean[cfg::B * cfg::C];
__device__ float g_inv [cfg::B * cfg::C];

// ---------------- tf32 helpers ----------------
__device__ __forceinline__ float tf32r(float x) {
    unsigned u;
    asm("cvt.rna.tf32.f32 %0, %1;" : "=r"(u) : "f"(x));
    return __uint_as_float(u);
}

__device__ __forceinline__ void mma8(float d[4], const float a[4], const float b[2]) {
    asm volatile(
        "mma.sync.aligned.m16n8k8.row.col.f32.tf32.tf32.f32 "
        "{%0,%1,%2,%3}, {%4,%5,%6,%7}, {%8,%9}, {%0,%1,%2,%3};"
        : "+f"(d[0]), "+f"(d[1]), "+f"(d[2]), "+f"(d[3])
        : "r"(__float_as_uint(a[0])), "r"(__float_as_uint(a[1])),
          "r"(__float_as_uint(a[2])), "r"(__float_as_uint(a[3])),
          "r"(__float_as_uint(b[0])), "r"(__float_as_uint(b[1])));
}

// ---------------- batched tf32 tensor-core GEMM ----------------
// C[z] = alpha * A[z] @ op(B[z]) (+ bias) (relu?) (+ resid)
// A row-major [M,K] lda; B row-major [K,N] ldb (or [N,K] ldb when TRANSB);
// per-batch offsets: z -> (zb, zh) = (z/Hdiv, z%Hdiv).
// Requires M%128==0, N%BN==0, K%32==0, 16B-aligned pointers (true here).
template<int BN, bool TRANSB>
__global__ void __launch_bounds__(256)
gemm_tf32(const float* __restrict__ Ag, const float* __restrict__ Bg,
          float* __restrict__ Cg, const float* __restrict__ bias,
          const float* __restrict__ resid,
          int M, int N, int K, int lda, int ldb, int ldc,
          long long sA1, long long sA2, long long sB1, long long sB2,
          long long sC1, long long sC2, int Hdiv, int biasStride,
          float alpha, int doRelu)
{
    constexpr int BM = 128, BK = 32, PAD = 4, LDSM = BK + PAD;
    constexpr int WARPS_M = (BN == 128) ? 2 : 4;
    constexpr int WM = BM / WARPS_M;               // 64 or 32
    constexpr int WN = BN / (8 / WARPS_M);         // 32
    constexpr int MA = WM / 16;                    // 4 or 2
    constexpr int NA = WN / 8;                     // 4
    constexpr int ATASK = BM * (BK / 4) / 256;     // 4
    constexpr int BTASK = BN * (BK / 4) / 256;     // 4 (BN=128) / 2 (BN=64)

    __shared__ __align__(16) float As[BM][LDSM];
    __shared__ __align__(16) float Bs[BN][LDSM];

    const int z  = blockIdx.z;
    const int zb = z / Hdiv, zh = z - zb * Hdiv;
    const float* A  = Ag + (long long)zb * sA1 + (long long)zh * sA2;
    const float* Bp = Bg + (long long)zb * sB1 + (long long)zh * sB2;
    float*       Cp = Cg + (long long)zb * sC1 + (long long)zh * sC2;
    const float* Rp = resid ? resid + (long long)zb * sC1 + (long long)zh * sC2 : nullptr;
    const float* bv = bias ? bias + zh * biasStride : nullptr;

    const int tid  = threadIdx.x;
    const int wid  = tid >> 5;
    const int lane = tid & 31;
    const int g    = lane >> 2;        // group id (0..7)
    const int tg   = lane & 3;         // thread-in-group
    const int wm   = (wid % WARPS_M) * WM;
    const int wn   = (wid / WARPS_M) * WN;
    const int rowBase = blockIdx.y * BM;
    const int colBase = blockIdx.x * BN;

    float acc[MA][NA][4];
    #pragma unroll
    for (int i = 0; i < MA; i++)
        #pragma unroll
        for (int j = 0; j < NA; j++)
            #pragma unroll
            for (int r = 0; r < 4; r++) acc[i][j][r] = 0.f;

    for (int kt = 0; kt < K; kt += BK) {
        // ---- A tile: row-major [M,K] -> As[m][k] (float4 along k) ----
        #pragma unroll
        for (int i = 0; i < ATASK; i++) {
            int idx = tid + i * 256;
            int row = idx >> 3;
            int kq  = (idx & 7) * 4;
            float4 f = *(const float4*)(A + (size_t)(rowBase + row) * lda + kt + kq);
            float4 t = make_float4(tf32r(f.x), tf32r(f.y), tf32r(f.z), tf32r(f.w));
            *(float4*)&As[row][kq] = t;
        }
        // ---- B tile -> Bs[n][k] ----
        if (TRANSB) {
            // B row-major [N,K]: float4 along k
            #pragma unroll
            for (int i = 0; i < BTASK; i++) {
                int idx = tid + i * 256;
                int n   = idx >> 3;
                int kq  = (idx & 7) * 4;
                float4 f = *(const float4*)(Bp + (size_t)(colBase + n) * ldb + kt + kq);
                float4 t = make_float4(tf32r(f.x), tf32r(f.y), tf32r(f.z), tf32r(f.w));
                *(float4*)&Bs[n][kq] = t;
            }
        } else {
            // B row-major [K,N]: gather 4 k's per (n) -> coalesced across lanes
            #pragma unroll
            for (int i = 0; i < BTASK; i++) {
                int idx = tid + i * 256;
                int n   = idx % BN;
                int k0  = (idx / BN) * 4;
                const float* bp0 = Bp + (size_t)(kt + k0) * ldb + colBase + n;
                float4 t;
                t.x = tf32r(bp0[0]);
                t.y = tf32r(bp0[(size_t)ldb]);
                t.z = tf32r(bp0[(size_t)2 * ldb]);
                t.w = tf32r(bp0[(size_t)3 * ldb]);
                *(float4*)&Bs[n][k0] = t;
            }
        }
        __syncthreads();

        // ---- compute: 4 k-steps of m16n8k8 ----
        #pragma unroll
        for (int ks = 0; ks < 4; ks++) {
            int k0 = ks * 8 + tg;
            float a[MA][4];
            #pragma unroll
            for (int i = 0; i < MA; i++) {
                int m = wm + i * 16 + g;
                a[i][0] = As[m][k0];
                a[i][1] = As[m + 8][k0];
                a[i][2] = As[m][k0 + 4];
                a[i][3] = As[m + 8][k0 + 4];
            }
            float b[NA][2];
            #pragma unroll
            for (int j = 0; j < NA; j++) {
                int n = wn + j * 8 + g;
                b[j][0] = Bs[n][k0];
                b[j][1] = Bs[n][k0 + 4];
            }
            #pragma unroll
            for (int i = 0; i < MA; i++)
                #pragma unroll
                for (int j = 0; j < NA; j++)
                    mma8(acc[i][j], a[i], b[j]);
        }
        __syncthreads();
    }

    // ---- epilogue: alpha, bias, relu, residual; float2 stores ----
    #pragma unroll
    for (int i = 0; i < MA; i++) {
        int r0 = rowBase + wm + i * 16 + g;
        #pragma unroll
        for (int j = 0; j < NA; j++) {
            int col = colBase + wn + j * 8 + 2 * tg;
            float2 v0 = make_float2(acc[i][j][0] * alpha, acc[i][j][1] * alpha);
            float2 v1 = make_float2(acc[i][j][2] * alpha, acc[i][j][3] * alpha);
            if (bv) {
                float2 bb = *(const float2*)&bv[col];
                v0.x += bb.x; v0.y += bb.y;
                v1.x += bb.x; v1.y += bb.y;
            }
            if (doRelu) {
                v0.x = fmaxf(v0.x, 0.f); v0.y = fmaxf(v0.y, 0.f);
                v1.x = fmaxf(v1.x, 0.f); v1.y = fmaxf(v1.y, 0.f);
            }
            size_t off0 = (size_t)r0 * ldc + col;
            size_t off1 = (size_t)(r0 + 8) * ldc + col;
            if (Rp) {
                float2 ra = *(const float2*)&Rp[off0];
                float2 rb = *(const float2*)&Rp[off1];
                v0.x += ra.x; v0.y += ra.y;
                v1.x += rb.x; v1.y += rb.y;
            }
            *(float2*)&Cp[off0] = v0;
            *(float2*)&Cp[off1] = v1;
        }
    }
}

// ---------------- LayerNorm over axis=1 (the T axis!), ddof=1, eps OUTSIDE sqrt ----
__global__ void ln_stats(const float* __restrict__ x,
                         float* __restrict__ ps, float* __restrict__ pq) {
    using namespace cfg;
    int gx = blockIdx.x;                 // 0..15 = b*8 + ctile
    int chunk = blockIdx.y;              // 0..15
    int b = gx >> 3, ct = gx & 7;
    int c = ct * 128 + threadIdx.x;
    const float* xp = x + ((size_t)b * T + (size_t)chunk * (T / NCHUNK)) * C + c;
    float s = 0.f, q = 0.f;
    #pragma unroll 4
    for (int r = 0; r < T / NCHUNK; r++) {
        float v = xp[(size_t)r * C];
        s += v; q += v * v;
    }
    int bc = b * C + c;
    ps[chunk * (B * C) + bc] = s;
    pq[chunk * (B * C) + bc] = q;
}

__global__ void ln_finalize(const float* __restrict__ ps, const float* __restrict__ pq,
                            float* __restrict__ meanb, float* __restrict__ invb) {
    using namespace cfg;
    int idx = blockIdx.x * blockDim.x + threadIdx.x;
    if (idx >= B * C) return;
    float s = 0.f, q = 0.f;
    #pragma unroll
    for (int ch = 0; ch < NCHUNK; ch++) {
        s += ps[ch * (B * C) + idx];
        q += pq[ch * (B * C) + idx];
    }
    float mean = s / (float)T;
    float var  = (q - s * s / (float)T) / (float)(T - 1);   // unbiased (ddof=1)
    meanb[idx] = mean;
    invb[idx]  = 1.f / (sqrtf(var) + EPS);                  // eps OUTSIDE sqrt
}

__global__ void ln_apply(const float* __restrict__ x, const float* __restrict__ meanb,
                         const float* __restrict__ invb, const float* __restrict__ gamma,
                         const float* __restrict__ beta, float* __restrict__ out) {
    using namespace cfg;
    size_t i4  = (size_t)blockIdx.x * blockDim.x + threadIdx.x;
    size_t idx = i4 * 4;
    int c  = (int)(idx % C);
    int b  = (int)(idx / ((size_t)T * C));
    int bc = b * C + c;
    float4 xv = *(const float4*)&x[idx];
    float4 gm = *(const float4*)&gamma[c];
    float4 bt = *(const float4*)&beta[c];
    float4 o;
    o.x = gm.x * ((xv.x - meanb[bc + 0]) * invb[bc + 0]) + bt.x;
    o.y = gm.y * ((xv.y - meanb[bc + 1]) * invb[bc + 1]) + bt.y;
    o.z = gm.z * ((xv.z - meanb[bc + 2]) * invb[bc + 2]) + bt.z;
    o.w = gm.w * ((xv.w - meanb[bc + 3]) * invb[bc + 3]) + bt.w;
    *(float4*)&out[idx] = o;
}

// ---------------- softmax over rows of S (row = 2048 contiguous floats) ----------------
__global__ void softmax_rows(float* __restrict__ S) {
    using namespace cfg;
    __shared__ float red[8];
    float* row = S + (size_t)blockIdx.x * T;
    int tid = threadIdx.x;
    float v[8];
    float mx = -3.4e38f;
    #pragma unroll
    for (int i = 0; i < 8; i++) { v[i] = row[tid + i * 256]; mx = fmaxf(mx, v[i]); }
    #pragma unroll
    for (int o = 16; o > 0; o >>= 1) mx = fmaxf(mx, __shfl_xor_sync(0xffffffffu, mx, o));
    if ((tid & 31) == 0) red[tid >> 5] = mx;
    __syncthreads();
    float m = red[0];
    #pragma unroll
    for (int w = 1; w < 8; w++) m = fmaxf(m, red[w]);
    __syncthreads();
    float s = 0.f;
    #pragma unroll
    for (int i = 0; i < 8; i++) { v[i] = __expf(v[i] - m); s += v[i]; }
    #pragma unroll
    for (int o = 16; o > 0; o >>= 1) s += __shfl_xor_sync(0xffffffffu, s, o);
    if ((tid & 31) == 0) red[tid >> 5] = s;
    __syncthreads();
    float tot = red[0];
    #pragma unroll
    for (int w = 1; w < 8; w++) tot += red[w];
    float inv = 1.f / tot;
    #pragma unroll
    for (int i = 0; i < 8; i++) row[tid + i * 256] = v[i] * inv;
}

// ---------------- launch ----------------
extern "C" void kernel_launch(void* const* d_in, const int* in_sizes, int n_in,
                              void* d_out, int out_size)
{
    using namespace cfg;
    const float* x   = (const float*)d_in[0];
    const float* Wq  = (const float*)d_in[1];
    const float* bq  = (const float*)d_in[2];
    const float* Wk  = (const float*)d_in[3];
    const float* bk  = (const float*)d_in[4];
    const float* Wv  = (const float*)d_in[5];
    const float* bvv = (const float*)d_in[6];
    const float* Wo  = (const float*)d_in[7];
    const float* bo  = (const float*)d_in[8];
    const float* W1  = (const float*)d_in[9];
    const float* b1  = (const float*)d_in[10];
    const float* W2  = (const float*)d_in[11];
    const float* b2  = (const float*)d_in[12];
    const float* g1  = (const float*)d_in[13];
    const float* be1 = (const float*)d_in[14];
    const float* g2  = (const float*)d_in[15];
    const float* be2 = (const float*)d_in[16];
    float* out = (float*)d_out;

    float *h1, *q, *k, *v, *S, *at, *x2, *h2, *f, *ps, *pq, *mean, *inv;
    cudaGetSymbolAddress((void**)&h1,   g_h1);
    cudaGetSymbolAddress((void**)&q,    g_q);
    cudaGetSymbolAddress((void**)&k,    g_k);
    cudaGetSymbolAddress((void**)&v,    g_v);
    cudaGetSymbolAddress((void**)&S,    g_S);
    cudaGetSymbolAddress((void**)&at,   g_at);
    cudaGetSymbolAddress((void**)&x2,   g_x2);
    cudaGetSymbolAddress((void**)&h2,   g_h2);
    cudaGetSymbolAddress((void**)&f,    g_f);
    cudaGetSymbolAddress((void**)&ps,   g_ps);
    cudaGetSymbolAddress((void**)&pq,   g_pq);
    cudaGetSymbolAddress((void**)&mean, g_mean);
    cudaGetSymbolAddress((void**)&inv,  g_inv);

    const long long TC   = (long long)T * C;
    const long long CHS  = (long long)C * HS;
    const long long THS  = (long long)T * HS;
    const long long HTHS = (long long)H * T * HS;
    const long long TT   = (long long)T * T;
    const long long HTT  = (long long)H * T * T;

    // ---- LN1: h1 = ln(x, gamma1, beta1)  (normalize over T) ----
    ln_stats<<<dim3(16, NCHUNK), 128>>>(x, ps, pq);
    ln_finalize<<<(B * C + 255) / 256, 256>>>(ps, pq, mean, inv);
    ln_apply<<<(B * T * C / 4) / 256, 256>>>(x, mean, inv, g1, be1, h1);

    // ---- QKV: [B,H,T,HS] = h1 @ W{q,k,v}[h] + b  (batched over (b,h)) ----
    dim3 gQKV(1, T / 128, B * H);
    gemm_tf32<64, false><<<gQKV, 256>>>(h1, Wq, q, bq, nullptr,
        T, HS, C, C, HS, HS,  TC, 0,  0, CHS,  HTHS, THS,  H, HS, 1.f, 0);
    gemm_tf32<64, false><<<gQKV, 256>>>(h1, Wk, k, bk, nullptr,
        T, HS, C, C, HS, HS,  TC, 0,  0, CHS,  HTHS, THS,  H, HS, 1.f, 0);
    gemm_tf32<64, false><<<gQKV, 256>>>(h1, Wv, v, bvv, nullptr,
        T, HS, C, C, HS, HS,  TC, 0,  0, CHS,  HTHS, THS,  H, HS, 1.f, 0);

    // ---- scores: S = (Q @ K^T) * HS^-0.5   (batched over B*H, B transposed) ----
    dim3 gS(T / 128, T / 128, B * H);
    gemm_tf32<128, true><<<gS, 256>>>(q, k, S, nullptr, nullptr,
        T, T, HS, HS, HS, T,  THS, 0,  THS, 0,  TT, 0,  1, 0, 0.125f, 0);

    // ---- softmax over keys ----
    softmax_rows<<<B * H * T, 256>>>(S);

    // ---- attn = S @ V, written head-concat into [B,T,C] ----
    gemm_tf32<64, false><<<gQKV, 256>>>(S, v, at, nullptr, nullptr,
        T, HS, T, T, HS, C,  HTT, TT,  HTHS, THS,  TC, (long long)HS,  H, 0, 1.f, 0);

    // ---- x2 = x + attn @ Wo + bo ----
    dim3 gWo(C / 128, BT / 128, 1);
    gemm_tf32<128, false><<<gWo, 256>>>(at, Wo, x2, bo, x,
        BT, C, C, C, C, C,  0, 0, 0, 0, 0, 0,  1, 0, 1.f, 0);

    // ---- LN2: h2 = ln(x2, gamma2, beta2) ----
    ln_stats<<<dim3(16, NCHUNK), 128>>>(x2, ps, pq);
    ln_finalize<<<(B * C + 255) / 256, 256>>>(ps, pq, mean, inv);
    ln_apply<<<(B * T * C / 4) / 256, 256>>>(x2, mean, inv, g2, be2, h2);

    // ---- FFN: out = x2 + relu(h2 @ W1 + b1) @ W2 + b2 ----
    dim3 gF1(FF / 128, BT / 128, 1);
    gemm_tf32<128, false><<<gF1, 256>>>(h2, W1, f, b1, nullptr,
        BT, FF, C, C, FF, FF,  0, 0, 0, 0, 0, 0,  1, 0, 1.f, 1);
    dim3 gF2(C / 128, BT / 128, 1);
    gemm_tf32<128, false><<<gF2, 256>>>(f, W2, out, b2, x2,
        BT, C, FF, FF, C, C,  0, 0, 0, 0, 0, 0,  1, 0, 1.f, 0);
}

// round 5
// speedup vs baseline: 2.4916x; 1.0923x over previous
#include <cuda_runtime.h>

// ---------------- problem constants (fixed shapes) ----------------
namespace cfg {
constexpr int B = 2, T = 2048, C = 1024, H = 16, HS = 64;
constexpr int BT = B * T;     // 4096
constexpr int FF = 4 * C;     // 4096
constexpr float EPS = 1e-5f;
constexpr int NCHUNK = 16;    // T reduction chunks for layernorm
}

// ---------------- scratch (device globals; no allocs allowed) ----------------
__device__ float g_h1[(size_t)cfg::B * cfg::T * cfg::C];
__device__ float g_q [(size_t)cfg::B * cfg::H * cfg::T * cfg::HS];
__device__ float g_k [(size_t)cfg::B * cfg::H * cfg::T * cfg::HS];
__device__ float g_v [(size_t)cfg::B * cfg::H * cfg::T * cfg::HS];
__device__ float g_S [(size_t)cfg::B * cfg::H * cfg::T * cfg::T];   // 512 MB scores
__device__ float g_at[(size_t)cfg::B * cfg::T * cfg::C];
__device__ float g_x2[(size_t)cfg::B * cfg::T * cfg::C];
__device__ float g_h2[(size_t)cfg::B * cfg::T * cfg::C];
__device__ float g_f [(size_t)cfg::B * cfg::T * cfg::FF];
__device__ float g_ps[cfg::NCHUNK * cfg::B * cfg::C];
__device__ float g_pq[cfg::NCHUNK * cfg::B * cfg::C];
__device__ float g_mean[cfg::B * cfg::C];
__device__ float g_inv [cfg::B * cfg::C];

// ---------------- tf32 / mma / ldmatrix helpers ----------------
__device__ __forceinline__ float tf32r(float x) {
    unsigned u;
    asm("cvt.rna.tf32.f32 %0, %1;" : "=r"(u) : "f"(x));
    return __uint_as_float(u);
}
__device__ __forceinline__ float4 tf32r4(float4 f) {
    return make_float4(tf32r(f.x), tf32r(f.y), tf32r(f.z), tf32r(f.w));
}

__device__ __forceinline__ void ldsm4(unsigned& r0, unsigned& r1, unsigned& r2,
                                      unsigned& r3, unsigned addr) {
    asm volatile("ldmatrix.sync.aligned.m8n8.x4.shared.b16 {%0,%1,%2,%3}, [%4];"
                 : "=r"(r0), "=r"(r1), "=r"(r2), "=r"(r3) : "r"(addr));
}

__device__ __forceinline__ void mma8(float d[4], const unsigned a[4],
                                     unsigned b0, unsigned b1) {
    asm volatile(
        "mma.sync.aligned.m16n8k8.row.col.f32.tf32.tf32.f32 "
        "{%0,%1,%2,%3}, {%4,%5,%6,%7}, {%8,%9}, {%0,%1,%2,%3};"
        : "+f"(d[0]), "+f"(d[1]), "+f"(d[2]), "+f"(d[3])
        : "r"(a[0]), "r"(a[1]), "r"(a[2]), "r"(a[3]), "r"(b0), "r"(b1));
}

// ---------------- batched tf32 tensor-core GEMM (ldmatrix + double buffer) ----
// C[z] = alpha * A[z] @ op(B[z]) (+ bias) (relu?) (+ resid)
// A row-major [M,K] lda; B row-major [K,N] ldb (or [N,K] ldb when TRANSB).
// Requires M%128==0, N%BN==0, K%32==0, 16B-aligned pointers (true here).
template<int BN, bool TRANSB>
__global__ void __launch_bounds__(256)
gemm_tc(const float* __restrict__ Ag, const float* __restrict__ Bg,
        float* __restrict__ Cg, const float* __restrict__ bias,
        const float* __restrict__ resid,
        int M, int N, int K, int lda, int ldb, int ldc,
        long long sA1, long long sA2, long long sB1, long long sB2,
        long long sC1, long long sC2, int Hdiv, int biasStride,
        float alpha, int doRelu)
{
    constexpr int BM = 128, BK = 32, PAD = 4, LDSM_ = BK + PAD;   // 36
    constexpr int WARPS_M = (BN == 128) ? 2 : 4;
    constexpr int WM = BM / WARPS_M;               // 64 or 32
    constexpr int WN = 32;                          // BN/(8/WARPS_M)
    constexpr int MA = WM / 16;                     // 4 or 2
    constexpr int NA = WN / 8;                      // 4
    constexpr int ATASK = BM * (BK / 4) / 256;      // 4 float4/thread
    constexpr int BTASK = BN * (BK / 4) / 256;      // 4 or 2
    constexpr int ASZ = BM * LDSM_;
    constexpr int BSZ = BN * LDSM_;

    extern __shared__ __align__(16) float smem[];
    float* Ab[2] = { smem,          smem + ASZ + BSZ };
    float* Bb[2] = { smem + ASZ,    smem + 2 * ASZ + BSZ };

    const int z  = blockIdx.z;
    const int zb = z / Hdiv, zh = z - zb * Hdiv;
    const float* A  = Ag + (long long)zb * sA1 + (long long)zh * sA2;
    const float* Bp = Bg + (long long)zb * sB1 + (long long)zh * sB2;
    float*       Cp = Cg + (long long)zb * sC1 + (long long)zh * sC2;
    const float* Rp = resid ? resid + (long long)zb * sC1 + (long long)zh * sC2 : nullptr;
    const float* bv = bias ? bias + zh * biasStride : nullptr;

    const int tid  = threadIdx.x;
    const int wid  = tid >> 5;
    const int lane = tid & 31;
    const int g    = lane >> 2;
    const int tg   = lane & 3;
    const int wm   = (wid % WARPS_M) * WM;
    const int wn   = (wid / WARPS_M) * WN;
    const int rowBase = blockIdx.y * BM;
    const int colBase = blockIdx.x * BN;

    // per-lane ldmatrix byte offsets (within a buffer)
    const int arow = (lane & 7) + ((lane >> 3) & 1) * 8;
    const int acol = (lane >> 4) * 4;
    const int brow = (lane & 7) + ((lane >> 4) & 1) * 8;
    const int bcol = ((lane >> 3) & 1) * 4;
    unsigned aoff[MA], boff[NA / 2];
    #pragma unroll
    for (int i = 0; i < MA; i++)
        aoff[i] = ((wm + i * 16 + arow) * LDSM_ + acol) * 4u;
    #pragma unroll
    for (int jj = 0; jj < NA / 2; jj++)
        boff[jj] = ((wn + jj * 16 + brow) * LDSM_ + bcol) * 4u;

    const unsigned sAbase[2] = { (unsigned)__cvta_generic_to_shared(Ab[0]),
                                 (unsigned)__cvta_generic_to_shared(Ab[1]) };
    const unsigned sBbase[2] = { (unsigned)__cvta_generic_to_shared(Bb[0]),
                                 (unsigned)__cvta_generic_to_shared(Bb[1]) };

    float acc[MA][NA][4];
    #pragma unroll
    for (int i = 0; i < MA; i++)
        #pragma unroll
        for (int j = 0; j < NA; j++)
            #pragma unroll
            for (int r = 0; r < 4; r++) acc[i][j][r] = 0.f;

    float4 ra[ATASK], rb[BTASK];

    // global tile load into registers
    auto loadG = [&](int kt) {
        #pragma unroll
        for (int i = 0; i < ATASK; i++) {
            int idx = tid + i * 256;
            int row = idx >> 3, kq = (idx & 7) * 4;
            ra[i] = *(const float4*)(A + (size_t)(rowBase + row) * lda + kt + kq);
        }
        if (TRANSB) {
            #pragma unroll
            for (int i = 0; i < BTASK; i++) {
                int idx = tid + i * 256;
                int n = idx >> 3, kq = (idx & 7) * 4;
                rb[i] = *(const float4*)(Bp + (size_t)(colBase + n) * ldb + kt + kq);
            }
        } else {
            #pragma unroll
            for (int i = 0; i < BTASK; i++) {
                int idx = tid + i * 256;
                int n = idx % BN, k0 = (idx / BN) * 4;
                const float* p0 = Bp + (size_t)(kt + k0) * ldb + colBase + n;
                rb[i].x = p0[0];
                rb[i].y = p0[(size_t)ldb];
                rb[i].z = p0[(size_t)2 * ldb];
                rb[i].w = p0[(size_t)3 * ldb];
            }
        }
    };
    // registers -> smem buffer p (tf32 round at store)
    auto stsT = [&](int p) {
        float (*As)[LDSM_] = (float (*)[LDSM_])Ab[p];
        float (*Bs)[LDSM_] = (float (*)[LDSM_])Bb[p];
        #pragma unroll
        for (int i = 0; i < ATASK; i++) {
            int idx = tid + i * 256;
            int row = idx >> 3, kq = (idx & 7) * 4;
            *(float4*)&As[row][kq] = tf32r4(ra[i]);
        }
        if (TRANSB) {
            #pragma unroll
            for (int i = 0; i < BTASK; i++) {
                int idx = tid + i * 256;
                int n = idx >> 3, kq = (idx & 7) * 4;
                *(float4*)&Bs[n][kq] = tf32r4(rb[i]);
            }
        } else {
            #pragma unroll
            for (int i = 0; i < BTASK; i++) {
                int idx = tid + i * 256;
                int n = idx % BN, k0 = (idx / BN) * 4;
                *(float4*)&Bs[n][k0] = tf32r4(rb[i]);
            }
        }
    };

    const int nk = K / BK;
    loadG(0);
    stsT(0);
    __syncthreads();

    int p = 0;
    for (int kt = 0; kt < nk; kt++) {
        if (kt + 1 < nk) loadG((kt + 1) * BK);

        const unsigned sA = sAbase[p], sB = sBbase[p];
        #pragma unroll
        for (int ks = 0; ks < 4; ks++) {
            unsigned a[MA][4], b[NA / 2][4];
            #pragma unroll
            for (int i = 0; i < MA; i++)
                ldsm4(a[i][0], a[i][1], a[i][2], a[i][3], sA + aoff[i] + ks * 32u);
            #pragma unroll
            for (int jj = 0; jj < NA / 2; jj++)
                ldsm4(b[jj][0], b[jj][1], b[jj][2], b[jj][3], sB + boff[jj] + ks * 32u);
            #pragma unroll
            for (int i = 0; i < MA; i++)
                #pragma unroll
                for (int j = 0; j < NA; j++)
                    mma8(acc[i][j], a[i], b[j >> 1][(j & 1) * 2],
                         b[j >> 1][(j & 1) * 2 + 1]);
        }

        if (kt + 1 < nk) {
            stsT(p ^ 1);
            __syncthreads();
            p ^= 1;
        }
    }

    // ---- epilogue: alpha, bias, relu, residual; float2 stores ----
    #pragma unroll
    for (int i = 0; i < MA; i++) {
        int r0 = rowBase + wm + i * 16 + g;
        #pragma unroll
        for (int j = 0; j < NA; j++) {
            int col = colBase + wn + j * 8 + 2 * tg;
            float2 v0 = make_float2(acc[i][j][0] * alpha, acc[i][j][1] * alpha);
            float2 v1 = make_float2(acc[i][j][2] * alpha, acc[i][j][3] * alpha);
            if (bv) {
                float2 bb = *(const float2*)&bv[col];
                v0.x += bb.x; v0.y += bb.y;
                v1.x += bb.x; v1.y += bb.y;
            }
            if (doRelu) {
                v0.x = fmaxf(v0.x, 0.f); v0.y = fmaxf(v0.y, 0.f);
                v1.x = fmaxf(v1.x, 0.f); v1.y = fmaxf(v1.y, 0.f);
            }
            size_t off0 = (size_t)r0 * ldc + col;
            size_t off1 = (size_t)(r0 + 8) * ldc + col;
            if (Rp) {
                float2 rr = *(const float2*)&Rp[off0];
                float2 rs = *(const float2*)&Rp[off1];
                v0.x += rr.x; v0.y += rr.y;
                v1.x += rs.x; v1.y += rs.y;
            }
            *(float2*)&Cp[off0] = v0;
            *(float2*)&Cp[off1] = v1;
        }
    }
}

// ---------------- LayerNorm over axis=1 (the T axis!), ddof=1, eps OUTSIDE sqrt ----
__global__ void ln_stats(const float* __restrict__ x,
                         float* __restrict__ ps, float* __restrict__ pq) {
    using namespace cfg;
    int gx = blockIdx.x;
    int chunk = blockIdx.y;
    int b = gx >> 3, ct = gx & 7;
    int c = ct * 128 + threadIdx.x;
    const float* xp = x + ((size_t)b * T + (size_t)chunk * (T / NCHUNK)) * C + c;
    float s = 0.f, q = 0.f;
    #pragma unroll 4
    for (int r = 0; r < T / NCHUNK; r++) {
        float v = xp[(size_t)r * C];
        s += v; q += v * v;
    }
    int bc = b * C + c;
    ps[chunk * (B * C) + bc] = s;
    pq[chunk * (B * C) + bc] = q;
}

__global__ void ln_finalize(const float* __restrict__ ps, const float* __restrict__ pq,
                            float* __restrict__ meanb, float* __restrict__ invb) {
    using namespace cfg;
    int idx = blockIdx.x * blockDim.x + threadIdx.x;
    if (idx >= B * C) return;
    float s = 0.f, q = 0.f;
    #pragma unroll
    for (int ch = 0; ch < NCHUNK; ch++) {
        s += ps[ch * (B * C) + idx];
        q += pq[ch * (B * C) + idx];
    }
    float mean = s / (float)T;
    float var  = (q - s * s / (float)T) / (float)(T - 1);   // unbiased (ddof=1)
    meanb[idx] = mean;
    invb[idx]  = 1.f / (sqrtf(var) + EPS);                  // eps OUTSIDE sqrt
}

__global__ void ln_apply(const float* __restrict__ x, const float* __restrict__ meanb,
                         const float* __restrict__ invb, const float* __restrict__ gamma,
                         const float* __restrict__ beta, float* __restrict__ out) {
    using namespace cfg;
    size_t i4  = (size_t)blockIdx.x * blockDim.x + threadIdx.x;
    size_t idx = i4 * 4;
    int c  = (int)(idx % C);
    int b  = (int)(idx / ((size_t)T * C));
    int bc = b * C + c;
    float4 xv = *(const float4*)&x[idx];
    float4 gm = *(const float4*)&gamma[c];
    float4 bt = *(const float4*)&beta[c];
    float4 o;
    o.x = gm.x * ((xv.x - meanb[bc + 0]) * invb[bc + 0]) + bt.x;
    o.y = gm.y * ((xv.y - meanb[bc + 1]) * invb[bc + 1]) + bt.y;
    o.z = gm.z * ((xv.z - meanb[bc + 2]) * invb[bc + 2]) + bt.z;
    o.w = gm.w * ((xv.w - meanb[bc + 3]) * invb[bc + 3]) + bt.w;
    *(float4*)&out[idx] = o;
}

// ---------------- softmax over rows of S ----------------
__global__ void softmax_rows(float* __restrict__ S) {
    using namespace cfg;
    __shared__ float red[8];
    float* row = S + (size_t)blockIdx.x * T;
    int tid = threadIdx.x;
    float v[8];
    float mx = -3.4e38f;
    #pragma unroll
    for (int i = 0; i < 8; i++) { v[i] = row[tid + i * 256]; mx = fmaxf(mx, v[i]); }
    #pragma unroll
    for (int o = 16; o > 0; o >>= 1) mx = fmaxf(mx, __shfl_xor_sync(0xffffffffu, mx, o));
    if ((tid & 31) == 0) red[tid >> 5] = mx;
    __syncthreads();
    float m = red[0];
    #pragma unroll
    for (int w = 1; w < 8; w++) m = fmaxf(m, red[w]);
    __syncthreads();
    float s = 0.f;
    #pragma unroll
    for (int i = 0; i < 8; i++) { v[i] = __expf(v[i] - m); s += v[i]; }
    #pragma unroll
    for (int o = 16; o > 0; o >>= 1) s += __shfl_xor_sync(0xffffffffu, s, o);
    if ((tid & 31) == 0) red[tid >> 5] = s;
    __syncthreads();
    float tot = red[0];
    #pragma unroll
    for (int w = 1; w < 8; w++) tot += red[w];
    float inv = 1.f / tot;
    #pragma unroll
    for (int i = 0; i < 8; i++) row[tid + i * 256] = v[i] * inv;
}

// ---------------- launch ----------------
extern "C" void kernel_launch(void* const* d_in, const int* in_sizes, int n_in,
                              void* d_out, int out_size)
{
    using namespace cfg;
    const float* x   = (const float*)d_in[0];
    const float* Wq  = (const float*)d_in[1];
    const float* bq  = (const float*)d_in[2];
    const float* Wk  = (const float*)d_in[3];
    const float* bk  = (const float*)d_in[4];
    const float* Wv  = (const float*)d_in[5];
    const float* bvv = (const float*)d_in[6];
    const float* Wo  = (const float*)d_in[7];
    const float* bo  = (const float*)d_in[8];
    const float* W1  = (const float*)d_in[9];
    const float* b1  = (const float*)d_in[10];
    const float* W2  = (const float*)d_in[11];
    const float* b2  = (const float*)d_in[12];
    const float* g1  = (const float*)d_in[13];
    const float* be1 = (const float*)d_in[14];
    const float* g2  = (const float*)d_in[15];
    const float* be2 = (const float*)d_in[16];
    float* out = (float*)d_out;

    float *h1, *q, *k, *v, *S, *at, *x2, *h2, *f, *ps, *pq, *mean, *inv;
    cudaGetSymbolAddress((void**)&h1,   g_h1);
    cudaGetSymbolAddress((void**)&q,    g_q);
    cudaGetSymbolAddress((void**)&k,    g_k);
    cudaGetSymbolAddress((void**)&v,    g_v);
    cudaGetSymbolAddress((void**)&S,    g_S);
    cudaGetSymbolAddress((void**)&at,   g_at);
    cudaGetSymbolAddress((void**)&x2,   g_x2);
    cudaGetSymbolAddress((void**)&h2,   g_h2);
    cudaGetSymbolAddress((void**)&f,    g_f);
    cudaGetSymbolAddress((void**)&ps,   g_ps);
    cudaGetSymbolAddress((void**)&pq,   g_pq);
    cudaGetSymbolAddress((void**)&mean, g_mean);
    cudaGetSymbolAddress((void**)&inv,  g_inv);

    const long long TC   = (long long)T * C;
    const long long CHS  = (long long)C * HS;
    const long long THS  = (long long)T * HS;
    const long long HTHS = (long long)H * T * HS;
    const long long TT   = (long long)T * T;
    const long long HTT  = (long long)H * T * T;

    constexpr int LDSM_ = 36;
    const int smem64  = (128 + 64)  * LDSM_ * 4 * 2;   // 55296 B
    const int smem128 = (128 + 128) * LDSM_ * 4 * 2;   // 73728 B
    static bool attrDone = false;
    if (!attrDone) {
        cudaFuncSetAttribute(gemm_tc<64,  false>, cudaFuncAttributeMaxDynamicSharedMemorySize, smem64);
        cudaFuncSetAttribute(gemm_tc<128, false>, cudaFuncAttributeMaxDynamicSharedMemorySize, smem128);
        cudaFuncSetAttribute(gemm_tc<128, true>,  cudaFuncAttributeMaxDynamicSharedMemorySize, smem128);
        attrDone = true;
    }

    // ---- LN1 ----
    ln_stats<<<dim3(16, NCHUNK), 128>>>(x, ps, pq);
    ln_finalize<<<(B * C + 255) / 256, 256>>>(ps, pq, mean, inv);
    ln_apply<<<(B * T * C / 4) / 256, 256>>>(x, mean, inv, g1, be1, h1);

    // ---- QKV ----
    dim3 gQKV(1, T / 128, B * H);
    gemm_tc<64, false><<<gQKV, 256, smem64>>>(h1, Wq, q, bq, nullptr,
        T, HS, C, C, HS, HS,  TC, 0,  0, CHS,  HTHS, THS,  H, HS, 1.f, 0);
    gemm_tc<64, false><<<gQKV, 256, smem64>>>(h1, Wk, k, bk, nullptr,
        T, HS, C, C, HS, HS,  TC, 0,  0, CHS,  HTHS, THS,  H, HS, 1.f, 0);
    gemm_tc<64, false><<<gQKV, 256, smem64>>>(h1, Wv, v, bvv, nullptr,
        T, HS, C, C, HS, HS,  TC, 0,  0, CHS,  HTHS, THS,  H, HS, 1.f, 0);

    // ---- scores: S = (Q @ K^T) * HS^-0.5 ----
    dim3 gS(T / 128, T / 128, B * H);
    gemm_tc<128, true><<<gS, 256, smem128>>>(q, k, S, nullptr, nullptr,
        T, T, HS, HS, HS, T,  THS, 0,  THS, 0,  TT, 0,  1, 0, 0.125f, 0);

    // ---- softmax ----
    softmax_rows<<<B * H * T, 256>>>(S);

    // ---- attn = S @ V (head-concat into [B,T,C]) ----
    gemm_tc<64, false><<<gQKV, 256, smem64>>>(S, v, at, nullptr, nullptr,
        T, HS, T, T, HS, C,  HTT, TT,  HTHS, THS,  TC, (long long)HS,  H, 0, 1.f, 0);

    // ---- x2 = x + attn @ Wo + bo ----
    dim3 gWo(C / 128, BT / 128, 1);
    gemm_tc<128, false><<<gWo, 256, smem128>>>(at, Wo, x2, bo, x,
        BT, C, C, C, C, C,  0, 0, 0, 0, 0, 0,  1, 0, 1.f, 0);

    // ---- LN2 ----
    ln_stats<<<dim3(16, NCHUNK), 128>>>(x2, ps, pq);
    ln_finalize<<<(B * C + 255) / 256, 256>>>(ps, pq, mean, inv);
    ln_apply<<<(B * T * C / 4) / 256, 256>>>(x2, mean, inv, g2, be2, h2);

    // ---- FFN ----
    dim3 gF1(FF / 128, BT / 128, 1);
    gemm_tc<128, false><<<gF1, 256, smem128>>>(h2, W1, f, b1, nullptr,
        BT, FF, C, C, FF, FF,  0, 0, 0, 0, 0, 0,  1, 0, 1.f, 1);
    dim3 gF2(C / 128, BT / 128, 1);
    gemm_tc<128, false><<<gF2, 256, smem128>>>(f, W2, out, b2, x2,
        BT, C, FF, FF, C, C,  0, 0, 0, 0, 0, 0,  1, 0, 1.f, 0);
}

// round 7
// speedup vs baseline: 2.8027x; 1.1249x over previous
#include <cuda_runtime.h>

// ---------------- problem constants (fixed shapes) ----------------
namespace cfg {
constexpr int B = 2, T = 2048, C = 1024, H = 16, HS = 64;
constexpr int BT = B * T;     // 4096
constexpr int FF = 4 * C;     // 4096
constexpr float EPS = 1e-5f;
constexpr int NCHUNK = 16;
}

// ---------------- scratch (device globals; no allocs allowed) ----------------
__device__ float g_h1[(size_t)cfg::B * cfg::T * cfg::C];
__device__ float g_q [(size_t)cfg::B * cfg::H * cfg::T * cfg::HS];
__device__ float g_k [(size_t)cfg::B * cfg::H * cfg::T * cfg::HS];
__device__ float g_v [(size_t)cfg::B * cfg::H * cfg::T * cfg::HS];
__device__ float g_vT[(size_t)cfg::B * cfg::H * cfg::HS * cfg::T];
__device__ float g_S [(size_t)cfg::B * cfg::H * cfg::T * cfg::T];   // 512 MB
__device__ float g_at[(size_t)cfg::B * cfg::T * cfg::C];
__device__ float g_x2[(size_t)cfg::B * cfg::T * cfg::C];
__device__ float g_h2[(size_t)cfg::B * cfg::T * cfg::C];
__device__ float g_f [(size_t)cfg::B * cfg::T * cfg::FF];
__device__ float g_wqT[(size_t)cfg::H * cfg::HS * cfg::C];
__device__ float g_wkT[(size_t)cfg::H * cfg::HS * cfg::C];
__device__ float g_wvT[(size_t)cfg::H * cfg::HS * cfg::C];
__device__ float g_woT[(size_t)cfg::C * cfg::C];
__device__ float g_w1T[(size_t)cfg::FF * cfg::C];
__device__ float g_w2T[(size_t)cfg::C * cfg::FF];
__device__ float g_ps[cfg::NCHUNK * cfg::B * cfg::C];
__device__ float g_pq[cfg::NCHUNK * cfg::B * cfg::C];
__device__ float g_mean[cfg::B * cfg::C];
__device__ float g_inv [cfg::B * cfg::C];

// ---------------- helpers ----------------
__device__ __forceinline__ float tf32r(float x) {
    unsigned u;
    asm("cvt.rna.tf32.f32 %0, %1;" : "=r"(u) : "f"(x));
    return __uint_as_float(u);
}

__device__ __forceinline__ void cpa16(unsigned dst, const float* src) {
    asm volatile("cp.async.cg.shared.global [%0], [%1], 16;" :: "r"(dst), "l"(src));
}
__device__ __forceinline__ void cpcommit() {
    asm volatile("cp.async.commit_group;");
}

__device__ __forceinline__ void ldsm4(unsigned& r0, unsigned& r1, unsigned& r2,
                                      unsigned& r3, unsigned addr) {
    asm volatile("ldmatrix.sync.aligned.m8n8.x4.shared.b16 {%0,%1,%2,%3}, [%4];"
                 : "=r"(r0), "=r"(r1), "=r"(r2), "=r"(r3) : "r"(addr));
}

__device__ __forceinline__ void mma8(float d[4], const unsigned a[4],
                                     unsigned b0, unsigned b1) {
    asm volatile(
        "mma.sync.aligned.m16n8k8.row.col.f32.tf32.tf32.f32 "
        "{%0,%1,%2,%3}, {%4,%5,%6,%7}, {%8,%9}, {%0,%1,%2,%3};"
        : "+f"(d[0]), "+f"(d[1]), "+f"(d[2]), "+f"(d[3])
        : "r"(a[0]), "r"(a[1]), "r"(a[2]), "r"(a[3]), "r"(b0), "r"(b1));
}

// ---------------- batched tf32 GEMM: all operands pre-tf32, B always [N,K] ----
// C[z] = alpha * A[z] @ B[z]^T (+ bias) (relu?) (+ resid) (cvtOut?)
template<int BM, int BN>
__global__ void __launch_bounds__(256)
gemm_tc(const float* __restrict__ Ag, const float* __restrict__ Bg,
        float* __restrict__ Cg, const float* __restrict__ bias,
        const float* __restrict__ resid,
        int K, int lda, int ldb, int ldc,
        long long sA1, long long sA2, long long sB1, long long sB2,
        long long sC1, long long sC2, int Hdiv, int biasStride,
        float alpha, int doRelu, int cvtOut)
{
    constexpr int BK = 32, LDSM_ = 36;          // 144B rows, conflict-free ldmatrix
    constexpr int WARPS_M = BM / 64;
    constexpr int MA = 4, NA = 4;               // warp tile 64x32
    constexpr int ATASK = BM / 32;              // float4 cp.asyncs per thread
    constexpr int BTASK = BN / 32;
    constexpr int STG = (BM + BN) * LDSM_;      // floats per stage

    extern __shared__ __align__(16) float smem[];
    const unsigned sbase = (unsigned)__cvta_generic_to_shared(smem);

    const int z  = blockIdx.z;
    const int zb = z / Hdiv, zh = z - zb * Hdiv;
    const float* A  = Ag + (long long)zb * sA1 + (long long)zh * sA2;
    const float* Bp = Bg + (long long)zb * sB1 + (long long)zh * sB2;
    float*       Cp = Cg + (long long)zb * sC1 + (long long)zh * sC2;
    const float* Rp = resid ? resid + (long long)zb * sC1 + (long long)zh * sC2 : nullptr;
    const float* bv = bias ? bias + zh * biasStride : nullptr;

    const int tid  = threadIdx.x;
    const int wid  = tid >> 5;
    const int lane = tid & 31;
    const int g    = lane >> 2;
    const int tg   = lane & 3;
    const int wm   = (wid % WARPS_M) * 64;
    const int wn   = (wid / WARPS_M) * 32;
    const int rowBase = blockIdx.y * BM;
    const int colBase = blockIdx.x * BN;

    // cp.async coordinates (fixed per thread)
    const int arow = tid >> 3;                   // with ATASK strides of 32 rows? no:
    // idx = tid + i*256 -> row = idx>>3 (0..BM-1), kq = (idx&7)*4
    // global srcs
    const float* aSrc[ATASK];
    const float* bSrc[BTASK];
    unsigned aDst[ATASK], bDst[BTASK];
    #pragma unroll
    for (int i = 0; i < ATASK; i++) {
        int idx = tid + i * 256;
        int row = idx >> 3, kq = (idx & 7) * 4;
        aSrc[i] = A + (size_t)(rowBase + row) * lda + kq;
        aDst[i] = sbase + (unsigned)(row * LDSM_ + kq) * 4u;
    }
    #pragma unroll
    for (int i = 0; i < BTASK; i++) {
        int idx = tid + i * 256;
        int n = idx >> 3, kq = (idx & 7) * 4;
        bSrc[i] = Bp + (size_t)(colBase + n) * ldb + kq;
        bDst[i] = sbase + (unsigned)((BM + n) * LDSM_ + kq) * 4u;
    }

    // ldmatrix lane offsets
    const int arow_l = (lane & 7) + ((lane >> 3) & 1) * 8;
    const int acol_l = (lane >> 4) * 4;
    const int brow_l = (lane & 7) + ((lane >> 4) & 1) * 8;
    const int bcol_l = ((lane >> 3) & 1) * 4;
    unsigned aoff[MA], boff[NA / 2];
    #pragma unroll
    for (int i = 0; i < MA; i++)
        aoff[i] = sbase + (unsigned)((wm + i * 16 + arow_l) * LDSM_ + acol_l) * 4u;
    #pragma unroll
    for (int jj = 0; jj < NA / 2; jj++)
        boff[jj] = sbase + (unsigned)((BM + wn + jj * 16 + brow_l) * LDSM_ + bcol_l) * 4u;

    float acc[MA][NA][4];
    #pragma unroll
    for (int i = 0; i < MA; i++)
        #pragma unroll
        for (int j = 0; j < NA; j++)
            #pragma unroll
            for (int r = 0; r < 4; r++) acc[i][j][r] = 0.f;

    const unsigned stgB = (unsigned)STG * 4u;    // stage stride in bytes

    auto issue = [&](int kt, int buf) {
        unsigned so = buf ? stgB : 0u;
        #pragma unroll
        for (int i = 0; i < ATASK; i++) cpa16(aDst[i] + so, aSrc[i] + kt * BK);
        #pragma unroll
        for (int i = 0; i < BTASK; i++) cpa16(bDst[i] + so, bSrc[i] + kt * BK);
    };

    const int nk = K / BK;
    issue(0, 0);
    cpcommit();

    for (int kt = 0; kt < nk; kt++) {
        if (kt + 1 < nk) {
            issue(kt + 1, (kt + 1) & 1);
            cpcommit();
            asm volatile("cp.async.wait_group 1;");
        } else {
            asm volatile("cp.async.wait_group 0;");
        }
        __syncthreads();

        const unsigned so = (kt & 1) ? stgB : 0u;
        #pragma unroll
        for (int ks = 0; ks < 4; ks++) {
            unsigned a[MA][4], b[NA / 2][4];
            #pragma unroll
            for (int i = 0; i < MA; i++)
                ldsm4(a[i][0], a[i][1], a[i][2], a[i][3], aoff[i] + so + ks * 32u);
            #pragma unroll
            for (int jj = 0; jj < NA / 2; jj++)
                ldsm4(b[jj][0], b[jj][1], b[jj][2], b[jj][3], boff[jj] + so + ks * 32u);
            #pragma unroll
            for (int i = 0; i < MA; i++)
                #pragma unroll
                for (int j = 0; j < NA; j++)
                    mma8(acc[i][j], a[i], b[j >> 1][(j & 1) * 2],
                         b[j >> 1][(j & 1) * 2 + 1]);
        }
        __syncthreads();
    }

    // ---- epilogue ----
    #pragma unroll
    for (int i = 0; i < MA; i++) {
        int r0 = rowBase + wm + i * 16 + g;
        #pragma unroll
        for (int j = 0; j < NA; j++) {
            int col = colBase + wn + j * 8 + 2 * tg;
            float2 v0 = make_float2(acc[i][j][0] * alpha, acc[i][j][1] * alpha);
            float2 v1 = make_float2(acc[i][j][2] * alpha, acc[i][j][3] * alpha);
            if (bv) {
                float2 bb = *(const float2*)&bv[col];
                v0.x += bb.x; v0.y += bb.y;
                v1.x += bb.x; v1.y += bb.y;
            }
            if (doRelu) {
                v0.x = fmaxf(v0.x, 0.f); v0.y = fmaxf(v0.y, 0.f);
                v1.x = fmaxf(v1.x, 0.f); v1.y = fmaxf(v1.y, 0.f);
            }
            size_t off0 = (size_t)r0 * ldc + col;
            size_t off1 = (size_t)(r0 + 8) * ldc + col;
            if (Rp) {
                float2 rr = *(const float2*)&Rp[off0];
                float2 rs = *(const float2*)&Rp[off1];
                v0.x += rr.x; v0.y += rr.y;
                v1.x += rs.x; v1.y += rs.y;
            }
            if (cvtOut) {
                v0.x = tf32r(v0.x); v0.y = tf32r(v0.y);
                v1.x = tf32r(v1.x); v1.y = tf32r(v1.y);
            }
            *(float2*)&Cp[off0] = v0;
            *(float2*)&Cp[off1] = v1;
        }
    }
}

// ---------------- batched transpose + tf32 convert: in [R,Cc] -> out [Cc,R] ----
__global__ void transpose_cvt(const float* __restrict__ in, float* __restrict__ out,
                              int R, int Cc, long long sIn, long long sOut) {
    __shared__ float t[32][33];
    int z = blockIdx.z;
    const float* ip = in + (long long)z * sIn;
    float* op = out + (long long)z * sOut;
    int c0 = blockIdx.x * 32, r0 = blockIdx.y * 32;
    #pragma unroll
    for (int i = threadIdx.y; i < 32; i += 8)
        t[i][threadIdx.x] = ip[(size_t)(r0 + i) * Cc + c0 + threadIdx.x];
    __syncthreads();
    #pragma unroll
    for (int i = threadIdx.y; i < 32; i += 8)
        op[(size_t)(c0 + i) * R + r0 + threadIdx.x] = tf32r(t[threadIdx.x][i]);
}

// ---------------- LayerNorm over axis=1 (T axis), ddof=1, eps OUTSIDE sqrt ----
__global__ void ln_stats(const float* __restrict__ x,
                         float* __restrict__ ps, float* __restrict__ pq) {
    using namespace cfg;
    int gx = blockIdx.x;
    int chunk = blockIdx.y;
    int b = gx >> 3, ct = gx & 7;
    int c = ct * 128 + threadIdx.x;
    const float* xp = x + ((size_t)b * T + (size_t)chunk * (T / NCHUNK)) * C + c;
    float s = 0.f, q = 0.f;
    #pragma unroll 4
    for (int r = 0; r < T / NCHUNK; r++) {
        float v = xp[(size_t)r * C];
        s += v; q += v * v;
    }
    int bc = b * C + c;
    ps[chunk * (B * C) + bc] = s;
    pq[chunk * (B * C) + bc] = q;
}

__global__ void ln_finalize(const float* __restrict__ ps, const float* __restrict__ pq,
                            float* __restrict__ meanb, float* __restrict__ invb) {
    using namespace cfg;
    int idx = blockIdx.x * blockDim.x + threadIdx.x;
    if (idx >= B * C) return;
    float s = 0.f, q = 0.f;
    #pragma unroll
    for (int ch = 0; ch < NCHUNK; ch++) {
        s += ps[ch * (B * C) + idx];
        q += pq[ch * (B * C) + idx];
    }
    float mean = s / (float)T;
    float var  = (q - s * s / (float)T) / (float)(T - 1);
    meanb[idx] = mean;
    invb[idx]  = 1.f / (sqrtf(var) + EPS);
}

// writes tf32-rounded output (consumed only by GEMMs)
__global__ void ln_apply(const float* __restrict__ x, const float* __restrict__ meanb,
                         const float* __restrict__ invb, const float* __restrict__ gamma,
                         const float* __restrict__ beta, float* __restrict__ out) {
    using namespace cfg;
    size_t i4  = (size_t)blockIdx.x * blockDim.x + threadIdx.x;
    size_t idx = i4 * 4;
    int c  = (int)(idx % C);
    int b  = (int)(idx / ((size_t)T * C));
    int bc = b * C + c;
    float4 xv = *(const float4*)&x[idx];
    float4 gm = *(const float4*)&gamma[c];
    float4 bt = *(const float4*)&beta[c];
    float4 o;
    o.x = tf32r(gm.x * ((xv.x - meanb[bc + 0]) * invb[bc + 0]) + bt.x);
    o.y = tf32r(gm.y * ((xv.y - meanb[bc + 1]) * invb[bc + 1]) + bt.y);
    o.z = tf32r(gm.z * ((xv.z - meanb[bc + 2]) * invb[bc + 2]) + bt.z);
    o.w = tf32r(gm.w * ((xv.w - meanb[bc + 3]) * invb[bc + 3]) + bt.w);
    *(float4*)&out[idx] = o;
}

// ---------------- softmax over rows of S (tf32-rounded output) ----------------
__global__ void softmax_rows(float* __restrict__ S) {
    using namespace cfg;
    __shared__ float red[8];
    float* row = S + (size_t)blockIdx.x * T;
    int tid = threadIdx.x;
    float v[8];
    float mx = -3.4e38f;
    #pragma unroll
    for (int i = 0; i < 8; i++) { v[i] = row[tid + i * 256]; mx = fmaxf(mx, v[i]); }
    #pragma unroll
    for (int o = 16; o > 0; o >>= 1) mx = fmaxf(mx, __shfl_xor_sync(0xffffffffu, mx, o));
    if ((tid & 31) == 0) red[tid >> 5] = mx;
    __syncthreads();
    float m = red[0];
    #pragma unroll
    for (int w = 1; w < 8; w++) m = fmaxf(m, red[w]);
    __syncthreads();
    float s = 0.f;
    #pragma unroll
    for (int i = 0; i < 8; i++) { v[i] = __expf(v[i] - m); s += v[i]; }
    #pragma unroll
    for (int o = 16; o > 0; o >>= 1) s += __shfl_xor_sync(0xffffffffu, s, o);
    if ((tid & 31) == 0) red[tid >> 5] = s;
    __syncthreads();
    float tot = red[0];
    #pragma unroll
    for (int w = 1; w < 8; w++) tot += red[w];
    float inv = 1.f / tot;
    #pragma unroll
    for (int i = 0; i < 8; i++) row[tid + i * 256] = tf32r(v[i] * inv);
}

// ---------------- launch ----------------
extern "C" void kernel_launch(void* const* d_in, const int* in_sizes, int n_in,
                              void* d_out, int out_size)
{
    using namespace cfg;
    const float* x   = (const float*)d_in[0];
    const float* Wq  = (const float*)d_in[1];
    const float* bq  = (const float*)d_in[2];
    const float* Wk  = (const float*)d_in[3];
    const float* bk  = (const float*)d_in[4];
    const float* Wv  = (const float*)d_in[5];
    const float* bvv = (const float*)d_in[6];
    const float* Wo  = (const float*)d_in[7];
    const float* bo  = (const float*)d_in[8];
    const float* W1  = (const float*)d_in[9];
    const float* b1  = (const float*)d_in[10];
    const float* W2  = (const float*)d_in[11];
    const float* b2  = (const float*)d_in[12];
    const float* g1  = (const float*)d_in[13];
    const float* be1 = (const float*)d_in[14];
    const float* g2  = (const float*)d_in[15];
    const float* be2 = (const float*)d_in[16];
    float* out = (float*)d_out;

    float *h1, *q, *k, *v, *vT, *S, *at, *x2, *h2, *f, *ps, *pq, *mean, *inv;
    float *wqT, *wkT, *wvT, *woT, *w1T, *w2T;
    cudaGetSymbolAddress((void**)&h1,   g_h1);
    cudaGetSymbolAddress((void**)&q,    g_q);
    cudaGetSymbolAddress((void**)&k,    g_k);
    cudaGetSymbolAddress((void**)&v,    g_v);
    cudaGetSymbolAddress((void**)&vT,   g_vT);
    cudaGetSymbolAddress((void**)&S,    g_S);
    cudaGetSymbolAddress((void**)&at,   g_at);
    cudaGetSymbolAddress((void**)&x2,   g_x2);
    cudaGetSymbolAddress((void**)&h2,   g_h2);
    cudaGetSymbolAddress((void**)&f,    g_f);
    cudaGetSymbolAddress((void**)&ps,   g_ps);
    cudaGetSymbolAddress((void**)&pq,   g_pq);
    cudaGetSymbolAddress((void**)&mean, g_mean);
    cudaGetSymbolAddress((void**)&inv,  g_inv);
    cudaGetSymbolAddress((void**)&wqT,  g_wqT);
    cudaGetSymbolAddress((void**)&wkT,  g_wkT);
    cudaGetSymbolAddress((void**)&wvT,  g_wvT);
    cudaGetSymbolAddress((void**)&woT,  g_woT);
    cudaGetSymbolAddress((void**)&w1T,  g_w1T);
    cudaGetSymbolAddress((void**)&w2T,  g_w2T);

    const long long TC   = (long long)T * C;
    const long long CHS  = (long long)C * HS;
    const long long THS  = (long long)T * HS;
    const long long HTHS = (long long)H * T * HS;
    const long long TT   = (long long)T * T;
    const long long HTT  = (long long)H * T * T;

    const int smemQ = (256 + 64)  * 36 * 4 * 2;   // 92160 B  (BM=256,BN=64)
    const int smemB = (128 + 128) * 36 * 4 * 2;   // 73728 B  (BM=128,BN=128)
    static bool attrDone = false;
    if (!attrDone) {
        cudaFuncSetAttribute(gemm_tc<256, 64>,  cudaFuncAttributeMaxDynamicSharedMemorySize, smemQ);
        cudaFuncSetAttribute(gemm_tc<128, 128>, cudaFuncAttributeMaxDynamicSharedMemorySize, smemB);
        attrDone = true;
    }

    // ---- weight prep: transpose + tf32 convert ----
    transpose_cvt<<<dim3(HS / 32, C / 32, H), dim3(32, 8)>>>(Wq, wqT, C, HS, CHS, CHS);
    transpose_cvt<<<dim3(HS / 32, C / 32, H), dim3(32, 8)>>>(Wk, wkT, C, HS, CHS, CHS);
    transpose_cvt<<<dim3(HS / 32, C / 32, H), dim3(32, 8)>>>(Wv, wvT, C, HS, CHS, CHS);
    transpose_cvt<<<dim3(C / 32, C / 32, 1), dim3(32, 8)>>>(Wo, woT, C, C, 0, 0);
    transpose_cvt<<<dim3(FF / 32, C / 32, 1), dim3(32, 8)>>>(W1, w1T, C, FF, 0, 0);
    transpose_cvt<<<dim3(C / 32, FF / 32, 1), dim3(32, 8)>>>(W2, w2T, FF, C, 0, 0);

    // ---- LN1 ----
    ln_stats<<<dim3(16, NCHUNK), 128>>>(x, ps, pq);
    ln_finalize<<<(B * C + 255) / 256, 256>>>(ps, pq, mean, inv);
    ln_apply<<<(B * T * C / 4) / 256, 256>>>(x, mean, inv, g1, be1, h1);

    // ---- QKV: per (b,h): [T,C] @ wT[h][64,C]^T ----
    dim3 gQKV(1, T / 256, B * H);
    gemm_tc<256, 64><<<gQKV, 256, smemQ>>>(h1, wqT, q, bq, nullptr,
        C, C, C, HS,  TC, 0,  0, CHS,  HTHS, THS,  H, HS, 1.f, 0, 1);
    gemm_tc<256, 64><<<gQKV, 256, smemQ>>>(h1, wkT, k, bk, nullptr,
        C, C, C, HS,  TC, 0,  0, CHS,  HTHS, THS,  H, HS, 1.f, 0, 1);
    gemm_tc<256, 64><<<gQKV, 256, smemQ>>>(h1, wvT, v, bvv, nullptr,
        C, C, C, HS,  TC, 0,  0, CHS,  HTHS, THS,  H, HS, 1.f, 0, 1);

    // ---- v -> vT per (b,h): [T,HS] -> [HS,T] ----
    transpose_cvt<<<dim3(HS / 32, T / 32, B * H), dim3(32, 8)>>>(v, vT, T, HS, THS, THS);

    // ---- scores: S = 0.125 * Q @ K^T  (K already [N=T, K=HS]) ----
    dim3 gS(T / 128, T / 128, B * H);
    gemm_tc<128, 128><<<gS, 256, smemB>>>(q, k, S, nullptr, nullptr,
        HS, HS, HS, T,  THS, 0,  THS, 0,  TT, 0,  1, 0, 0.125f, 0, 0);

    // ---- softmax ----
    softmax_rows<<<B * H * T, 256>>>(S);

    // ---- attn = S @ vT^T  (head-concat into [B,T,C]) ----
    dim3 gAV(1, T / 256, B * H);
    gemm_tc<256, 64><<<gAV, 256, smemQ>>>(S, vT, at, nullptr, nullptr,
        T, T, T, C,  HTT, TT,  HTHS, THS,  TC, (long long)HS,  H, 0, 1.f, 0, 1);

    // ---- x2 = x + attn @ Wo + bo ----
    dim3 gWo(C / 128, BT / 128, 1);
    gemm_tc<128, 128><<<gWo, 256, smemB>>>(at, woT, x2, bo, x,
        C, C, C, C,  0, 0, 0, 0, 0, 0,  1, 0, 1.f, 0, 0);

    // ---- LN2 ----
    ln_stats<<<dim3(16, NCHUNK), 128>>>(x2, ps, pq);
    ln_finalize<<<(B * C + 255) / 256, 256>>>(ps, pq, mean, inv);
    ln_apply<<<(B * T * C / 4) / 256, 256>>>(x2, mean, inv, g2, be2, h2);

    // ---- FFN ----
    dim3 gF1(FF / 128, BT / 128, 1);
    gemm_tc<128, 128><<<gF1, 256, smemB>>>(h2, w1T, f, b1, nullptr,
        C, C, C, FF,  0, 0, 0, 0, 0, 0,  1, 0, 1.f, 1, 1);
    dim3 gF2(C / 128, BT / 128, 1);
    gemm_tc<128, 128><<<gF2, 256, smemB>>>(f, w2T, out, b2, x2,
        FF, FF, FF, C,  0, 0, 0, 0, 0, 0,  1, 0, 1.f, 0, 0);
}

// round 10
// speedup vs baseline: 3.4418x; 1.2280x over previous
#include <cuda_runtime.h>

// ---------------- problem constants (fixed shapes) ----------------
namespace cfg {
constexpr int B = 2, T = 2048, C = 1024, H = 16, HS = 64;
constexpr int BT = B * T;     // 4096
constexpr int FF = 4 * C;     // 4096
constexpr float EPS = 1e-5f;
constexpr int NCHUNK = 16;
}

// ---------------- scratch (device globals; no allocs allowed) ----------------
__device__ float g_h1[(size_t)cfg::B * cfg::T * cfg::C];
__device__ float g_q [(size_t)cfg::B * cfg::H * cfg::T * cfg::HS];
__device__ float g_k [(size_t)cfg::B * cfg::H * cfg::T * cfg::HS];
__device__ float g_v [(size_t)cfg::B * cfg::H * cfg::T * cfg::HS];
__device__ float g_vT[(size_t)cfg::B * cfg::H * cfg::HS * cfg::T];
__device__ float g_at[(size_t)cfg::B * cfg::T * cfg::C];
__device__ float g_x2[(size_t)cfg::B * cfg::T * cfg::C];
__device__ float g_h2[(size_t)cfg::B * cfg::T * cfg::C];
__device__ float g_f [(size_t)cfg::B * cfg::T * cfg::FF];
__device__ float g_wqT[(size_t)cfg::H * cfg::HS * cfg::C];
__device__ float g_wkT[(size_t)cfg::H * cfg::HS * cfg::C];
__device__ float g_wvT[(size_t)cfg::H * cfg::HS * cfg::C];
__device__ float g_woT[(size_t)cfg::C * cfg::C];
__device__ float g_w1T[(size_t)cfg::FF * cfg::C];
__device__ float g_w2T[(size_t)cfg::C * cfg::FF];
__device__ float g_ps[cfg::NCHUNK * cfg::B * cfg::C];
__device__ float g_pq[cfg::NCHUNK * cfg::B * cfg::C];
__device__ float g_mean[cfg::B * cfg::C];
__device__ float g_inv [cfg::B * cfg::C];

// ---------------- helpers ----------------
__device__ __forceinline__ float tf32r(float x) {
    unsigned u;
    asm("cvt.rna.tf32.f32 %0, %1;" : "=r"(u) : "f"(x));
    return __uint_as_float(u);
}

__device__ __forceinline__ void cpa16(unsigned dst, const float* src) {
    asm volatile("cp.async.cg.shared.global [%0], [%1], 16;" :: "r"(dst), "l"(src));
}
__device__ __forceinline__ void cpcommit() {
    asm volatile("cp.async.commit_group;");
}

__device__ __forceinline__ void ldsm4(unsigned& r0, unsigned& r1, unsigned& r2,
                                      unsigned& r3, unsigned addr) {
    asm volatile("ldmatrix.sync.aligned.m8n8.x4.shared.b16 {%0,%1,%2,%3}, [%4];"
                 : "=r"(r0), "=r"(r1), "=r"(r2), "=r"(r3) : "r"(addr));
}

__device__ __forceinline__ void mma8(float d[4], const unsigned a[4],
                                     unsigned b0, unsigned b1) {
    asm volatile(
        "mma.sync.aligned.m16n8k8.row.col.f32.tf32.tf32.f32 "
        "{%0,%1,%2,%3}, {%4,%5,%6,%7}, {%8,%9}, {%0,%1,%2,%3};"
        : "+f"(d[0]), "+f"(d[1]), "+f"(d[2]), "+f"(d[3])
        : "r"(a[0]), "r"(a[1]), "r"(a[2]), "r"(a[3]), "r"(b0), "r"(b1));
}

// ---------------- batched tf32 GEMM: all operands pre-tf32, B always [N,K] ----
template<int BM, int BN>
__global__ void __launch_bounds__(256)
gemm_tc(const float* __restrict__ Ag, const float* __restrict__ Bg,
        float* __restrict__ Cg, const float* __restrict__ bias,
        const float* __restrict__ resid,
        int K, int lda, int ldb, int ldc,
        long long sA1, long long sA2, long long sB1, long long sB2,
        long long sC1, long long sC2, int Hdiv, int biasStride,
        float alpha, int doRelu, int cvtOut)
{
    constexpr int BK = 32, LDSM_ = 36;
    constexpr int WARPS_M = BM / 64;
    constexpr int MA = 4, NA = 4;
    constexpr int ATASK = BM / 32;
    constexpr int BTASK = BN / 32;
    constexpr int STG = (BM + BN) * LDSM_;

    extern __shared__ __align__(16) float smem[];
    const unsigned sbase = (unsigned)__cvta_generic_to_shared(smem);

    const int z  = blockIdx.z;
    const int zb = z / Hdiv, zh = z - zb * Hdiv;
    const float* A  = Ag + (long long)zb * sA1 + (long long)zh * sA2;
    const float* Bp = Bg + (long long)zb * sB1 + (long long)zh * sB2;
    float*       Cp = Cg + (long long)zb * sC1 + (long long)zh * sC2;
    const float* Rp = resid ? resid + (long long)zb * sC1 + (long long)zh * sC2 : nullptr;
    const float* bv = bias ? bias + zh * biasStride : nullptr;

    const int tid  = threadIdx.x;
    const int wid  = tid >> 5;
    const int lane = tid & 31;
    const int g    = lane >> 2;
    const int tg   = lane & 3;
    const int wm   = (wid % WARPS_M) * 64;
    const int wn   = (wid / WARPS_M) * 32;
    const int rowBase = blockIdx.y * BM;
    const int colBase = blockIdx.x * BN;

    const float* aSrc[ATASK];
    const float* bSrc[BTASK];
    unsigned aDst[ATASK], bDst[BTASK];
    #pragma unroll
    for (int i = 0; i < ATASK; i++) {
        int idx = tid + i * 256;
        int row = idx >> 3, kq = (idx & 7) * 4;
        aSrc[i] = A + (size_t)(rowBase + row) * lda + kq;
        aDst[i] = sbase + (unsigned)(row * LDSM_ + kq) * 4u;
    }
    #pragma unroll
    for (int i = 0; i < BTASK; i++) {
        int idx = tid + i * 256;
        int n = idx >> 3, kq = (idx & 7) * 4;
        bSrc[i] = Bp + (size_t)(colBase + n) * ldb + kq;
        bDst[i] = sbase + (unsigned)((BM + n) * LDSM_ + kq) * 4u;
    }

    const int arow_l = (lane & 7) + ((lane >> 3) & 1) * 8;
    const int acol_l = (lane >> 4) * 4;
    const int brow_l = (lane & 7) + ((lane >> 4) & 1) * 8;
    const int bcol_l = ((lane >> 3) & 1) * 4;
    unsigned aoff[MA], boff[NA / 2];
    #pragma unroll
    for (int i = 0; i < MA; i++)
        aoff[i] = sbase + (unsigned)((wm + i * 16 + arow_l) * LDSM_ + acol_l) * 4u;
    #pragma unroll
    for (int jj = 0; jj < NA / 2; jj++)
        boff[jj] = sbase + (unsigned)((BM + wn + jj * 16 + brow_l) * LDSM_ + bcol_l) * 4u;

    float acc[MA][NA][4];
    #pragma unroll
    for (int i = 0; i < MA; i++)
        #pragma unroll
        for (int j = 0; j < NA; j++)
            #pragma unroll
            for (int r = 0; r < 4; r++) acc[i][j][r] = 0.f;

    const unsigned stgB = (unsigned)STG * 4u;

    auto issue = [&](int kt, int buf) {
        unsigned so = buf ? stgB : 0u;
        #pragma unroll
        for (int i = 0; i < ATASK; i++) cpa16(aDst[i] + so, aSrc[i] + kt * BK);
        #pragma unroll
        for (int i = 0; i < BTASK; i++) cpa16(bDst[i] + so, bSrc[i] + kt * BK);
    };

    const int nk = K / BK;
    issue(0, 0);
    cpcommit();

    for (int kt = 0; kt < nk; kt++) {
        if (kt + 1 < nk) {
            issue(kt + 1, (kt + 1) & 1);
            cpcommit();
            asm volatile("cp.async.wait_group 1;");
        } else {
            asm volatile("cp.async.wait_group 0;");
        }
        __syncthreads();

        const unsigned so = (kt & 1) ? stgB : 0u;
        #pragma unroll
        for (int ks = 0; ks < 4; ks++) {
            unsigned a[MA][4], b[NA / 2][4];
            #pragma unroll
            for (int i = 0; i < MA; i++)
                ldsm4(a[i][0], a[i][1], a[i][2], a[i][3], aoff[i] + so + ks * 32u);
            #pragma unroll
            for (int jj = 0; jj < NA / 2; jj++)
                ldsm4(b[jj][0], b[jj][1], b[jj][2], b[jj][3], boff[jj] + so + ks * 32u);
            #pragma unroll
            for (int i = 0; i < MA; i++)
                #pragma unroll
                for (int j = 0; j < NA; j++)
                    mma8(acc[i][j], a[i], b[j >> 1][(j & 1) * 2],
                         b[j >> 1][(j & 1) * 2 + 1]);
        }
        __syncthreads();
    }

    #pragma unroll
    for (int i = 0; i < MA; i++) {
        int r0 = rowBase + wm + i * 16 + g;
        #pragma unroll
        for (int j = 0; j < NA; j++) {
            int col = colBase + wn + j * 8 + 2 * tg;
            float2 v0 = make_float2(acc[i][j][0] * alpha, acc[i][j][1] * alpha);
            float2 v1 = make_float2(acc[i][j][2] * alpha, acc[i][j][3] * alpha);
            if (bv) {
                float2 bb = *(const float2*)&bv[col];
                v0.x += bb.x; v0.y += bb.y;
                v1.x += bb.x; v1.y += bb.y;
            }
            if (doRelu) {
                v0.x = fmaxf(v0.x, 0.f); v0.y = fmaxf(v0.y, 0.f);
                v1.x = fmaxf(v1.x, 0.f); v1.y = fmaxf(v1.y, 0.f);
            }
            size_t off0 = (size_t)r0 * ldc + col;
            size_t off1 = (size_t)(r0 + 8) * ldc + col;
            if (Rp) {
                float2 rr = *(const float2*)&Rp[off0];
                float2 rs = *(const float2*)&Rp[off1];
                v0.x += rr.x; v0.y += rr.y;
                v1.x += rs.x; v1.y += rs.y;
            }
            if (cvtOut) {
                v0.x = tf32r(v0.x); v0.y = tf32r(v0.y);
                v1.x = tf32r(v1.x); v1.y = tf32r(v1.y);
            }
            *(float2*)&Cp[off0] = v0;
            *(float2*)&Cp[off1] = v1;
        }
    }
}

// ---------------- fused flash attention ----------------
// grid: (T/128, B*H). 8 warps; each warp owns 16 full Q rows.
// Q [B*H][T][HS] (tf32 values), K [B*H][T][HS] (tf32), vT [B*H][HS][T] (tf32).
// out: g_at [B][T][C] head-concat, tf32-rounded.
__global__ void __launch_bounds__(256)
flash_attn(const float* __restrict__ Qg, const float* __restrict__ Kg,
           const float* __restrict__ vTg, float* __restrict__ Og)
{
    using namespace cfg;
    constexpr int ST = 68;                       // smem row stride (floats)
    constexpr int PQ_FLOATS = 128 * ST;          // Q-stage / P region
    constexpr int TILE_FLOATS = 64 * ST;         // one 64x64 tile
    const unsigned tileBytes  = TILE_FLOATS * 4u;
    const unsigned stageBytes = 2u * tileBytes;  // K + vT per stage

    extern __shared__ __align__(16) float sm[];
    float* Psm = sm;

    const int q0 = blockIdx.x * 128;
    const int z  = blockIdx.y;
    const int b  = z >> 4, h = z & 15;

    const float* Qb = Qg + ((size_t)z * T + q0) * HS;
    const float* Kb = Kg + (size_t)z * T * HS;
    const float* Vb = vTg + (size_t)z * HS * T;
    float* Ob = Og + ((size_t)b * T + q0) * C + h * HS;

    const int tid = threadIdx.x, wid = tid >> 5, lane = tid & 31;
    const int g = lane >> 2, tg = lane & 3;
    const int wq = wid * 16;

    const unsigned sb = (unsigned)__cvta_generic_to_shared(sm);
    const unsigned kB = sb + (unsigned)PQ_FLOATS * 4u;

    const int arow_l = (lane & 7) + ((lane >> 3) & 1) * 8;
    const int acol_l = (lane >> 4) * 4;
    const int brow_l = (lane & 7) + ((lane >> 4) & 1) * 8;
    const int bcol_l = ((lane >> 3) & 1) * 4;

    const unsigned aoffP = sb + (unsigned)((wq + arow_l) * ST + acol_l) * 4u;
    unsigned boffT[4];
    #pragma unroll
    for (int jj = 0; jj < 4; jj++)
        boffT[jj] = (unsigned)((jj * 16 + brow_l) * ST + bcol_l) * 4u;

    // ---- stage Q into P region, extract A fragments to registers ----
    #pragma unroll
    for (int i = 0; i < 8; i++) {
        int idx = tid + i * 256;
        int row = idx >> 4, c4 = (idx & 15) * 4;
        cpa16(sb + (unsigned)(row * ST + c4) * 4u, Qb + (size_t)row * HS + c4);
    }
    cpcommit();

    auto issueKV = [&](int it, int buf) {
        int t0 = it * 64;
        unsigned so = kB + (buf ? stageBytes : 0u);
        #pragma unroll
        for (int i = 0; i < 4; i++) {
            int idx = tid + i * 256;
            int row = idx >> 4, c4 = (idx & 15) * 4;
            cpa16(so + (unsigned)(row * ST + c4) * 4u,
                  Kb + (size_t)(t0 + row) * HS + c4);
        }
        #pragma unroll
        for (int i = 0; i < 4; i++) {
            int idx = tid + i * 256;
            int row = idx >> 4, c4 = (idx & 15) * 4;
            cpa16(so + tileBytes + (unsigned)(row * ST + c4) * 4u,
                  Vb + (size_t)row * T + t0 + c4);
        }
    };

    issueKV(0, 0);
    cpcommit();
    asm volatile("cp.async.wait_group 1;");   // Q ready
    __syncthreads();

    unsigned qa[8][4];
    #pragma unroll
    for (int ks = 0; ks < 8; ks++)
        ldsm4(qa[ks][0], qa[ks][1], qa[ks][2], qa[ks][3], aoffP + ks * 32u);

    float o[8][4];
    #pragma unroll
    for (int j = 0; j < 8; j++)
        #pragma unroll
        for (int r = 0; r < 4; r++) o[j][r] = 0.f;
    float m0 = -1e30f, m1 = -1e30f, l0 = 0.f, l1 = 0.f;

    const int NIT = T / 64;   // 32
    for (int it = 0; it < NIT; it++) {
        if (it + 1 < NIT) {
            issueKV(it + 1, (it + 1) & 1);
            cpcommit();
            asm volatile("cp.async.wait_group 1;");
        } else {
            asm volatile("cp.async.wait_group 0;");
        }
        __syncthreads();

        const unsigned kBase = kB + ((it & 1) ? stageBytes : 0u);
        const unsigned vBase = kBase + tileBytes;

        // ---- S = Q @ K^T (warp rows x 64 keys) ----
        float s[8][4];
        #pragma unroll
        for (int j = 0; j < 8; j++)
            #pragma unroll
            for (int r = 0; r < 4; r++) s[j][r] = 0.f;
        #pragma unroll
        for (int ks = 0; ks < 8; ks++) {
            unsigned bk[4][4];
            #pragma unroll
            for (int jj = 0; jj < 4; jj++)
                ldsm4(bk[jj][0], bk[jj][1], bk[jj][2], bk[jj][3],
                      kBase + boffT[jj] + ks * 32u);
            #pragma unroll
            for (int j = 0; j < 8; j++)
                mma8(s[j], qa[ks], bk[j >> 1][(j & 1) * 2],
                     bk[j >> 1][(j & 1) * 2 + 1]);
        }

        // ---- online softmax (rows g and g+8, warp-local) ----
        float mt0 = -1e30f, mt1 = -1e30f;
        #pragma unroll
        for (int j = 0; j < 8; j++) {
            mt0 = fmaxf(mt0, fmaxf(s[j][0], s[j][1]));
            mt1 = fmaxf(mt1, fmaxf(s[j][2], s[j][3]));
        }
        mt0 *= 0.125f; mt1 *= 0.125f;
        mt0 = fmaxf(mt0, __shfl_xor_sync(0xffffffffu, mt0, 1));
        mt0 = fmaxf(mt0, __shfl_xor_sync(0xffffffffu, mt0, 2));
        mt1 = fmaxf(mt1, __shfl_xor_sync(0xffffffffu, mt1, 1));
        mt1 = fmaxf(mt1, __shfl_xor_sync(0xffffffffu, mt1, 2));
        float mn0 = fmaxf(m0, mt0), mn1 = fmaxf(m1, mt1);
        float rf0 = __expf(m0 - mn0), rf1 = __expf(m1 - mn1);

        float sum0 = 0.f, sum1 = 0.f;
        float* prow0 = Psm + (wq + g) * ST + 2 * tg;
        float* prow1 = Psm + (wq + g + 8) * ST + 2 * tg;
        #pragma unroll
        for (int j = 0; j < 8; j++) {
            float p0 = __expf(s[j][0] * 0.125f - mn0);
            float p1 = __expf(s[j][1] * 0.125f - mn0);
            float p2 = __expf(s[j][2] * 0.125f - mn1);
            float p3 = __expf(s[j][3] * 0.125f - mn1);
            sum0 += p0 + p1; sum1 += p2 + p3;
            *(float2*)(prow0 + j * 8) = make_float2(tf32r(p0), tf32r(p1));
            *(float2*)(prow1 + j * 8) = make_float2(tf32r(p2), tf32r(p3));
        }
        sum0 += __shfl_xor_sync(0xffffffffu, sum0, 1);
        sum0 += __shfl_xor_sync(0xffffffffu, sum0, 2);
        sum1 += __shfl_xor_sync(0xffffffffu, sum1, 1);
        sum1 += __shfl_xor_sync(0xffffffffu, sum1, 2);
        l0 = l0 * rf0 + sum0;
        l1 = l1 * rf1 + sum1;
        m0 = mn0; m1 = mn1;
        #pragma unroll
        for (int j = 0; j < 8; j++) {
            o[j][0] *= rf0; o[j][1] *= rf0;
            o[j][2] *= rf1; o[j][3] *= rf1;
        }
        __syncwarp();

        // ---- O += P @ V  (B operand = vT tile [d][keys]) ----
        #pragma unroll
        for (int ks = 0; ks < 8; ks++) {
            unsigned pa[4];
            ldsm4(pa[0], pa[1], pa[2], pa[3], aoffP + ks * 32u);
            unsigned bv_[4][4];
            #pragma unroll
            for (int jj = 0; jj < 4; jj++)
                ldsm4(bv_[jj][0], bv_[jj][1], bv_[jj][2], bv_[jj][3],
                      vBase + boffT[jj] + ks * 32u);
            #pragma unroll
            for (int j = 0; j < 8; j++)
                mma8(o[j], pa, bv_[j >> 1][(j & 1) * 2],
                     bv_[j >> 1][(j & 1) * 2 + 1]);
        }
        __syncthreads();
    }

    // ---- epilogue: normalize by l, write head-concat, tf32-rounded ----
    float inv0 = 1.f / l0, inv1 = 1.f / l1;
    #pragma unroll
    for (int j = 0; j < 8; j++) {
        int col = j * 8 + 2 * tg;
        size_t off0 = (size_t)(wq + g) * C + col;
        size_t off1 = (size_t)(wq + g + 8) * C + col;
        *(float2*)&Ob[off0] = make_float2(tf32r(o[j][0] * inv0), tf32r(o[j][1] * inv0));
        *(float2*)&Ob[off1] = make_float2(tf32r(o[j][2] * inv1), tf32r(o[j][3] * inv1));
    }
}

// ---------------- batched transpose + tf32 convert: in [R,Cc] -> out [Cc,R] ----
__global__ void transpose_cvt(const float* __restrict__ in, float* __restrict__ out,
                              int R, int Cc, long long sIn, long long sOut) {
    __shared__ float t[32][33];
    int z = blockIdx.z;
    const float* ip = in + (long long)z * sIn;
    float* op = out + (long long)z * sOut;
    int c0 = blockIdx.x * 32, r0 = blockIdx.y * 32;
    #pragma unroll
    for (int i = threadIdx.y; i < 32; i += 8)
        t[i][threadIdx.x] = ip[(size_t)(r0 + i) * Cc + c0 + threadIdx.x];
    __syncthreads();
    #pragma unroll
    for (int i = threadIdx.y; i < 32; i += 8)
        op[(size_t)(c0 + i) * R + r0 + threadIdx.x] = tf32r(t[threadIdx.x][i]);
}

// ---------------- LayerNorm over axis=1 (T axis), ddof=1, eps OUTSIDE sqrt ----
__global__ void ln_stats(const float* __restrict__ x,
                         float* __restrict__ ps, float* __restrict__ pq) {
    using namespace cfg;
    int gx = blockIdx.x;
    int chunk = blockIdx.y;
    int b = gx >> 3, ct = gx & 7;
    int c = ct * 128 + threadIdx.x;
    const float* xp = x + ((size_t)b * T + (size_t)chunk * (T / NCHUNK)) * C + c;
    float s = 0.f, q = 0.f;
    #pragma unroll 4
    for (int r = 0; r < T / NCHUNK; r++) {
        float v = xp[(size_t)r * C];
        s += v; q += v * v;
    }
    int bc = b * C + c;
    ps[chunk * (B * C) + bc] = s;
    pq[chunk * (B * C) + bc] = q;
}

__global__ void ln_finalize(const float* __restrict__ ps, const float* __restrict__ pq,
                            float* __restrict__ meanb, float* __restrict__ invb) {
    using namespace cfg;
    int idx = blockIdx.x * blockDim.x + threadIdx.x;
    if (idx >= B * C) return;
    float s = 0.f, q = 0.f;
    #pragma unroll
    for (int ch = 0; ch < NCHUNK; ch++) {
        s += ps[ch * (B * C) + idx];
        q += pq[ch * (B * C) + idx];
    }
    float mean = s / (float)T;
    float var  = (q - s * s / (float)T) / (float)(T - 1);
    meanb[idx] = mean;
    invb[idx]  = 1.f / (sqrtf(var) + EPS);
}

__global__ void ln_apply(const float* __restrict__ x, const float* __restrict__ meanb,
                         const float* __restrict__ invb, const float* __restrict__ gamma,
                         const float* __restrict__ beta, float* __restrict__ out) {
    using namespace cfg;
    size_t i4  = (size_t)blockIdx.x * blockDim.x + threadIdx.x;
    size_t idx = i4 * 4;
    int c  = (int)(idx % C);
    int b  = (int)(idx / ((size_t)T * C));
    int bc = b * C + c;
    float4 xv = *(const float4*)&x[idx];
    float4 gm = *(const float4*)&gamma[c];
    float4 bt = *(const float4*)&beta[c];
    float4 o;
    o.x = tf32r(gm.x * ((xv.x - meanb[bc + 0]) * invb[bc + 0]) + bt.x);
    o.y = tf32r(gm.y * ((xv.y - meanb[bc + 1]) * invb[bc + 1]) + bt.y);
    o.z = tf32r(gm.z * ((xv.z - meanb[bc + 2]) * invb[bc + 2]) + bt.z);
    o.w = tf32r(gm.w * ((xv.w - meanb[bc + 3]) * invb[bc + 3]) + bt.w);
    *(float4*)&out[idx] = o;
}

// ---------------- launch ----------------
extern "C" void kernel_launch(void* const* d_in, const int* in_sizes, int n_in,
                              void* d_out, int out_size)
{
    using namespace cfg;
    const float* x   = (const float*)d_in[0];
    const float* Wq  = (const float*)d_in[1];
    const float* bq  = (const float*)d_in[2];
    const float* Wk  = (const float*)d_in[3];
    const float* bk  = (const float*)d_in[4];
    const float* Wv  = (const float*)d_in[5];
    const float* bvv = (const float*)d_in[6];
    const float* Wo  = (const float*)d_in[7];
    const float* bo  = (const float*)d_in[8];
    const float* W1  = (const float*)d_in[9];
    const float* b1  = (const float*)d_in[10];
    const float* W2  = (const float*)d_in[11];
    const float* b2  = (const float*)d_in[12];
    const float* g1  = (const float*)d_in[13];
    const float* be1 = (const float*)d_in[14];
    const float* g2  = (const float*)d_in[15];
    const float* be2 = (const float*)d_in[16];
    float* out = (float*)d_out;

    float *h1, *q, *k, *v, *vT, *at, *x2, *h2, *f, *ps, *pq, *mean, *inv;
    float *wqT, *wkT, *wvT, *woT, *w1T, *w2T;
    cudaGetSymbolAddress((void**)&h1,   g_h1);
    cudaGetSymbolAddress((void**)&q,    g_q);
    cudaGetSymbolAddress((void**)&k,    g_k);
    cudaGetSymbolAddress((void**)&v,    g_v);
    cudaGetSymbolAddress((void**)&vT,   g_vT);
    cudaGetSymbolAddress((void**)&at,   g_at);
    cudaGetSymbolAddress((void**)&x2,   g_x2);
    cudaGetSymbolAddress((void**)&h2,   g_h2);
    cudaGetSymbolAddress((void**)&f,    g_f);
    cudaGetSymbolAddress((void**)&ps,   g_ps);
    cudaGetSymbolAddress((void**)&pq,   g_pq);
    cudaGetSymbolAddress((void**)&mean, g_mean);
    cudaGetSymbolAddress((void**)&inv,  g_inv);
    cudaGetSymbolAddress((void**)&wqT,  g_wqT);
    cudaGetSymbolAddress((void**)&wkT,  g_wkT);
    cudaGetSymbolAddress((void**)&wvT,  g_wvT);
    cudaGetSymbolAddress((void**)&woT,  g_woT);
    cudaGetSymbolAddress((void**)&w1T,  g_w1T);
    cudaGetSymbolAddress((void**)&w2T,  g_w2T);

    const long long TC   = (long long)T * C;
    const long long CHS  = (long long)C * HS;
    const long long THS  = (long long)T * HS;
    const long long HTHS = (long long)H * T * HS;

    const int smemQ = (256 + 64)  * 36 * 4 * 2;   // 92160 B
    const int smemB = (128 + 128) * 36 * 4 * 2;   // 73728 B
    const int smemF = (128 * 68 + 4 * 64 * 68) * 4;  // 104448 B
    static bool attrDone = false;
    if (!attrDone) {
        cudaFuncSetAttribute(gemm_tc<256, 64>,  cudaFuncAttributeMaxDynamicSharedMemorySize, smemQ);
        cudaFuncSetAttribute(gemm_tc<128, 128>, cudaFuncAttributeMaxDynamicSharedMemorySize, smemB);
        cudaFuncSetAttribute(flash_attn,        cudaFuncAttributeMaxDynamicSharedMemorySize, smemF);
        attrDone = true;
    }

    // ---- weight prep: transpose + tf32 convert ----
    transpose_cvt<<<dim3(HS / 32, C / 32, H), dim3(32, 8)>>>(Wq, wqT, C, HS, CHS, CHS);
    transpose_cvt<<<dim3(HS / 32, C / 32, H), dim3(32, 8)>>>(Wk, wkT, C, HS, CHS, CHS);
    transpose_cvt<<<dim3(HS / 32, C / 32, H), dim3(32, 8)>>>(Wv, wvT, C, HS, CHS, CHS);
    transpose_cvt<<<dim3(C / 32, C / 32, 1), dim3(32, 8)>>>(Wo, woT, C, C, 0, 0);
    transpose_cvt<<<dim3(FF / 32, C / 32, 1), dim3(32, 8)>>>(W1, w1T, C, FF, 0, 0);
    transpose_cvt<<<dim3(C / 32, FF / 32, 1), dim3(32, 8)>>>(W2, w2T, FF, C, 0, 0);

    // ---- LN1 ----
    ln_stats<<<dim3(16, NCHUNK), 128>>>(x, ps, pq);
    ln_finalize<<<(B * C + 255) / 256, 256>>>(ps, pq, mean, inv);
    ln_apply<<<(B * T * C / 4) / 256, 256>>>(x, mean, inv, g1, be1, h1);

    // ---- QKV ----
    dim3 gQKV(1, T / 256, B * H);
    gemm_tc<256, 64><<<gQKV, 256, smemQ>>>(h1, wqT, q, bq, nullptr,
        C, C, C, HS,  TC, 0,  0, CHS,  HTHS, THS,  H, HS, 1.f, 0, 1);
    gemm_tc<256, 64><<<gQKV, 256, smemQ>>>(h1, wkT, k, bk, nullptr,
        C, C, C, HS,  TC, 0,  0, CHS,  HTHS, THS,  H, HS, 1.f, 0, 1);
    gemm_tc<256, 64><<<gQKV, 256, smemQ>>>(h1, wvT, v, bvv, nullptr,
        C, C, C, HS,  TC, 0,  0, CHS,  HTHS, THS,  H, HS, 1.f, 0, 1);

    // ---- v -> vT per (b,h): [T,HS] -> [HS,T] ----
    transpose_cvt<<<dim3(HS / 32, T / 32, B * H), dim3(32, 8)>>>(v, vT, T, HS, THS, THS);

    // ---- fused attention: S=QK^T -> softmax -> O=PV, head-concat into at ----
    flash_attn<<<dim3(T / 128, B * H), 256, smemF>>>(q, k, vT, at);

    // ---- x2 = x + attn @ Wo + bo ----
    dim3 gWo(C / 128, BT / 128, 1);
    gemm_tc<128, 128><<<gWo, 256, smemB>>>(at, woT, x2, bo, x,
        C, C, C, C,  0, 0, 0, 0, 0, 0,  1, 0, 1.f, 0, 0);

    // ---- LN2 ----
    ln_stats<<<dim3(16, NCHUNK), 128>>>(x2, ps, pq);
    ln_finalize<<<(B * C + 255) / 256, 256>>>(ps, pq, mean, inv);
    ln_apply<<<(B * T * C / 4) / 256, 256>>>(x2, mean, inv, g2, be2, h2);

    // ---- FFN ----
    dim3 gF1(FF / 128, BT / 128, 1);
    gemm_tc<128, 128><<<gF1, 256, smemB>>>(h2, w1T, f, b1, nullptr,
        C, C, C, FF,  0, 0, 0, 0, 0, 0,  1, 0, 1.f, 1, 1);
    dim3 gF2(C / 128, BT / 128, 1);
    gemm_tc<128, 128><<<gF2, 256, smemB>>>(f, w2T, out, b2, x2,
        FF, FF, FF, C,  0, 0, 0, 0, 0, 0,  1, 0, 1.f, 0, 0);
}